// round 9
// baseline (speedup 1.0000x reference)
#include <cuda_runtime.h>
#include <cstdint>

#define Bq   8
#define Nn   5000
#define Ee   40000
#define Ff   64
#define FEe  16
#define FIL  96
#define DM   144
#define DU   160
#define LN_EPS 1e-3f
#define MSTR 104   // Ms row stride (words) — conflict-free

__device__ __align__(16) float g_agg[(size_t)Bq * Nn * FIL];

// ---------------- helpers ----------------
__device__ __forceinline__ void red4(float* addr, float4 v) {
    asm volatile("red.global.add.v4.f32 [%0], {%1,%2,%3,%4};"
                 :: "l"(addr), "f"(v.x), "f"(v.y), "f"(v.z), "f"(v.w) : "memory");
}
// split (x,y) fp32 pair into bf16x2 hi + bf16x2 lo (lo = residual)
__device__ __forceinline__ uint32_t split_pair(float x, float y, uint32_t& lo2) {
    uint32_t h;
    asm("cvt.rn.bf16x2.f32 %0, %1, %2;" : "=r"(h) : "f"(y), "f"(x));
    float hx = __uint_as_float(h << 16);
    float hy = __uint_as_float(h & 0xffff0000u);
    float rx = x - hx, ry = y - hy;
    asm("cvt.rn.bf16x2.f32 %0, %1, %2;" : "=r"(lo2) : "f"(ry), "f"(rx));
    return h;
}
__device__ __forceinline__ void mma_bf16(float* c, const uint32_t* a,
                                         uint32_t b0, uint32_t b1) {
    asm volatile(
        "mma.sync.aligned.m16n8k16.row.col.f32.bf16.bf16.f32 "
        "{%0,%1,%2,%3}, {%4,%5,%6,%7}, {%8,%9}, {%0,%1,%2,%3};"
        : "+f"(c[0]), "+f"(c[1]), "+f"(c[2]), "+f"(c[3])
        : "r"(a[0]), "r"(a[1]), "r"(a[2]), "r"(a[3]), "r"(b0), "r"(b1));
}
__device__ __forceinline__ void load_split(const float* p, int off,
                                           uint32_t& h0, uint32_t& h2,
                                           uint32_t& l0, uint32_t& l2) {
    float2 x0 = *(const float2*)(p + off);
    float2 x2 = *(const float2*)(p + off + 8);
    h0 = split_pair(x0.x, x0.y, l0);
    h2 = split_pair(x2.x, x2.y, l2);
}

__global__ void zero_agg_kernel() {
    const size_t n4 = (size_t)Bq * Nn * FIL / 4;
    float4* p = (float4*)g_agg;
    for (size_t i = (size_t)blockIdx.x * blockDim.x + threadIdx.x; i < n4;
         i += (size_t)gridDim.x * blockDim.x)
        p[i] = make_float4(0.f, 0.f, 0.f, 0.f);
}

// ================= edge kernel =================
// 128 edges/block, 8 warps x 16 rows; 9 k-steps, 3 MMA terms.
// B16[slot][n'] : uint4 {bh_k2a, bh_k2b, bl_k2a, bl_k2b}, slot = kt*4+q,
// n' = n ^ (2q). Ms (stride 104) overlays B16 after the MMA loop.
#define ES_B16   0            // 36*96 uint4 = 13824 words (55.3 KB)
#define ES_BM    13824
#define ES_GM    13920
#define ES_BT    14016
#define ES_MEAN  14112        // 128
#define ES_RSTD  14240        // 128
#define ES_SEB   14368        // 128 int2 = 256 words
#define ES_TOTAL 14624
#define E_SMEM_BYTES (ES_TOTAL * 4)

__global__ void __launch_bounds__(256, 2) edge_kernel_mma(
    const float* __restrict__ nodes, const float* __restrict__ ef,
    const int*   __restrict__ edges, const float* __restrict__ Wm,
    const float* __restrict__ bm,    const float* __restrict__ gm,
    const float* __restrict__ bt,    float* __restrict__ msg_out)
{
    extern __shared__ float sm[];
    uint4* B16  = (uint4*)sm;
    float* Ms   = sm;                 // overlay after MMA, stride MSTR
    float* bm_s = sm + ES_BM;
    float* gm_s = sm + ES_GM;
    float* bt_s = sm + ES_BT;
    float* mn_s = sm + ES_MEAN;
    float* rs_s = sm + ES_RSTD;
    int2*  seb  = (int2*)(sm + ES_SEB);

    const int t = threadIdx.x;

    // ---- stage weights as paired hi/lo uint4 ----
    for (int i = t; i < 36 * 96; i += 256) {
        int slot = i / 96, n = i - slot * 96;
        int kt = slot >> 2, q = slot & 3;
        int k2a = kt * 8 + q, k2b = k2a + 4;
        uint32_t la, lb;
        uint32_t ha = split_pair(Wm[(2 * k2a) * FIL + n], Wm[(2 * k2a + 1) * FIL + n], la);
        uint32_t hb = split_pair(Wm[(2 * k2b) * FIL + n], Wm[(2 * k2b + 1) * FIL + n], lb);
        B16[slot * 96 + (n ^ (2 * q))] = make_uint4(ha, hb, la, lb);
    }
    if (t < FIL) { bm_s[t] = bm[t]; gm_s[t] = gm[t]; bt_s[t] = bt[t]; }
    if (t < 128) seb[t] = ((const int2*)edges)[blockIdx.x * 128 + t];
    __syncthreads();

    const int lane = t & 31;
    const int w    = t >> 5;          // 0..7
    const int g    = lane >> 2;
    const int q    = lane & 3;
    const int r0 = w * 16 + g, r1 = r0 + 8;

    const int ge0 = blockIdx.x * 128 + r0;
    const int ge1 = ge0 + 8;
    const int b0 = ge0 / Ee, b1 = ge1 / Ee;
    const int2 e0 = seb[r0], e1 = seb[r1];

    const float* s0 = nodes + ((size_t)b0 * Nn + e0.x) * Ff;
    const float* s1 = nodes + ((size_t)b1 * Nn + e1.x) * Ff;
    const float* d0 = nodes + ((size_t)b0 * Nn + e0.y) * Ff;
    const float* d1 = nodes + ((size_t)b1 * Nn + e1.y) * Ff;
    const float* f0 = ef + (size_t)ge0 * FEe;
    const float* f1 = ef + (size_t)ge1 * FEe;

    float c[12][4];
    #pragma unroll
    for (int nt = 0; nt < 12; nt++) { c[nt][0]=0.f; c[nt][1]=0.f; c[nt][2]=0.f; c[nt][3]=0.f; }

    const int gsw = g ^ (2 * q);
    const int qo  = 2 * q;

    // prefetch kt=0 raw values
    float2 ra0 = *(const float2*)(s0 + qo);
    float2 ra2 = *(const float2*)(s0 + qo + 8);
    float2 rb0 = *(const float2*)(s1 + qo);
    float2 rb2 = *(const float2*)(s1 + qo + 8);

    #pragma unroll
    for (int kt = 0; kt < 9; kt++) {
        uint32_t ah[4], al[4];
        ah[0] = split_pair(ra0.x, ra0.y, al[0]);
        ah[1] = split_pair(rb0.x, rb0.y, al[1]);
        ah[2] = split_pair(ra2.x, ra2.y, al[2]);
        ah[3] = split_pair(rb2.x, rb2.y, al[3]);

        if (kt < 8) {   // prefetch next k-step while MMAs run
            const int kn = kt + 1;
            const float *p0, *p1;
            int off;
            if (kn < 4)      { p0 = s0; p1 = s1; off = kn * 16; }
            else if (kn < 8) { p0 = d0; p1 = d1; off = (kn - 4) * 16; }
            else             { p0 = f0; p1 = f1; off = 0; }
            off += qo;
            ra0 = *(const float2*)(p0 + off);
            ra2 = *(const float2*)(p0 + off + 8);
            rb0 = *(const float2*)(p1 + off);
            rb2 = *(const float2*)(p1 + off + 8);
        }

        const uint4* Bp = B16 + (kt * 4 + q) * 96 + gsw;
        #pragma unroll
        for (int nt = 0; nt < 12; nt++) {
            uint4 Bv = Bp[nt * 8];
            mma_bf16(c[nt], ah, Bv.x, Bv.y);
            mma_bf16(c[nt], al, Bv.x, Bv.y);
            mma_bf16(c[nt], ah, Bv.z, Bv.w);
        }
    }

    // ---- bias + relu + LN stats (quad owns rows r0, r1) ----
    float sum0 = 0.f, sq0 = 0.f, sum1 = 0.f, sq1 = 0.f;
    #pragma unroll
    for (int nt = 0; nt < 12; nt++) {
        const int j = nt * 8 + 2 * q;
        const float bv0 = bm_s[j], bv1 = bm_s[j + 1];
        float v0 = fmaxf(c[nt][0] + bv0, 0.f);
        float v1 = fmaxf(c[nt][1] + bv1, 0.f);
        float v2 = fmaxf(c[nt][2] + bv0, 0.f);
        float v3 = fmaxf(c[nt][3] + bv1, 0.f);
        c[nt][0] = v0; c[nt][1] = v1; c[nt][2] = v2; c[nt][3] = v3;
        sum0 += v0 + v1;  sq0 += v0 * v0 + v1 * v1;
        sum1 += v2 + v3;  sq1 += v2 * v2 + v3 * v3;
    }
    #pragma unroll
    for (int m = 1; m < 4; m <<= 1) {
        sum0 += __shfl_xor_sync(0xffffffffu, sum0, m);
        sq0  += __shfl_xor_sync(0xffffffffu, sq0,  m);
        sum1 += __shfl_xor_sync(0xffffffffu, sum1, m);
        sq1  += __shfl_xor_sync(0xffffffffu, sq1,  m);
    }
    if (q == 0) {
        float mean = sum0 * (1.f / FIL);
        float var  = sq0 * (1.f / FIL) - mean * mean;
        mn_s[r0] = mean; rs_s[r0] = rsqrtf(var + LN_EPS);
        mean = sum1 * (1.f / FIL);
        var  = sq1 * (1.f / FIL) - mean * mean;
        mn_s[r1] = mean; rs_s[r1] = rsqrtf(var + LN_EPS);
    }
    __syncthreads();   // all warps done with B16 -> safe to overlay Ms

    #pragma unroll
    for (int nt = 0; nt < 12; nt++) {
        const int j = nt * 8 + 2 * q;
        *(float2*)(Ms + r0 * MSTR + j) = make_float2(c[nt][0], c[nt][1]);
        *(float2*)(Ms + r1 * MSTR + j) = make_float2(c[nt][2], c[nt][3]);
    }
    __syncthreads();

    // ---- output: LN apply + coalesced store + vector atomics ----
    for (int i = t; i < 128 * 24; i += 256) {
        const int row = i / 24;
        const int c4  = i - row * 24;
        const int j   = c4 * 4;
        const float mean = mn_s[row], rstd = rs_s[row];
        float4 v = *(const float4*)(Ms + row * MSTR + j);
        float4 o;
        o.x = (v.x - mean) * rstd * gm_s[j + 0] + bt_s[j + 0];
        o.y = (v.y - mean) * rstd * gm_s[j + 1] + bt_s[j + 1];
        o.z = (v.z - mean) * rstd * gm_s[j + 2] + bt_s[j + 2];
        o.w = (v.w - mean) * rstd * gm_s[j + 3] + bt_s[j + 3];
        const int ge = blockIdx.x * 128 + row;
        const int b  = ge / Ee;
        ((float4*)(msg_out + (size_t)ge * FIL))[c4] = o;
        red4(g_agg + ((size_t)b * Nn + seb[row].y) * FIL + j, o);
    }
}

// ================= node kernel (unchanged from R8) =================
#define NS_B16   0            // 40*96 uint4 = 15360 words (61.4 KB)
#define NS_BM    15360
#define NS_GM    15456
#define NS_BT    15552
#define NS_MEAN  15648
#define NS_RSTD  15776
#define NS_TOTAL 15904
#define N_SMEM_BYTES (NS_TOTAL * 4)

__global__ void __launch_bounds__(128) node_kernel_mma(
    const float* __restrict__ nodes, const float* __restrict__ Wu,
    const float* __restrict__ bu,    const float* __restrict__ gm,
    const float* __restrict__ bt,    float* __restrict__ upd_out)
{
    extern __shared__ float sm[];
    uint4* B16  = (uint4*)sm;
    float* Ms   = sm;
    float* bm_s = sm + NS_BM;
    float* gm_s = sm + NS_GM;
    float* bt_s = sm + NS_BT;
    float* mn_s = sm + NS_MEAN;
    float* rs_s = sm + NS_RSTD;

    const int t = threadIdx.x;

    for (int i = t; i < 40 * 96; i += 128) {
        int slot = i / 96, n = i - slot * 96;
        int kt = slot >> 2, q = slot & 3;
        int k2a = kt * 8 + q, k2b = k2a + 4;
        uint32_t la, lb;
        uint32_t ha = split_pair(Wu[(2 * k2a) * FIL + n], Wu[(2 * k2a + 1) * FIL + n], la);
        uint32_t hb = split_pair(Wu[(2 * k2b) * FIL + n], Wu[(2 * k2b + 1) * FIL + n], lb);
        B16[slot * 96 + (n ^ (2 * q))] = make_uint4(ha, hb, la, lb);
    }
    if (t < FIL) { bm_s[t] = bu[t]; gm_s[t] = gm[t]; bt_s[t] = bt[t]; }
    __syncthreads();

    const int lane = t & 31;
    const int w    = t >> 5;
    const int g    = lane >> 2;
    const int q    = lane & 3;
    const int r0 = w * 32 + g, r1 = r0 + 8, r2 = r0 + 16, r3 = r0 + 24;

    const int NT = Bq * Nn;
    int gn[4] = {blockIdx.x * 128 + r0, blockIdx.x * 128 + r1,
                 blockIdx.x * 128 + r2, blockIdx.x * 128 + r3};
    const float* np[4];
    const float* ap[4];
    #pragma unroll
    for (int rr = 0; rr < 4; rr++) {
        int gc = gn[rr] < NT ? gn[rr] : NT - 1;
        int b = gc / Nn, n = gc - b * Nn;
        np[rr] = nodes + ((size_t)b * Nn + n) * Ff;
        ap[rr] = g_agg + ((size_t)b * Nn + n) * FIL;
    }

    float c0[12][4], c1[12][4];
    #pragma unroll
    for (int nt = 0; nt < 12; nt++) {
        c0[nt][0]=0.f; c0[nt][1]=0.f; c0[nt][2]=0.f; c0[nt][3]=0.f;
        c1[nt][0]=0.f; c1[nt][1]=0.f; c1[nt][2]=0.f; c1[nt][3]=0.f;
    }
    const int gsw = g ^ (2 * q);

    #pragma unroll
    for (int kt = 0; kt < 10; kt++) {
        const float *pa, *pb, *pc, *pd;
        int off;
        if (kt < 4) { pa=np[0]; pb=np[1]; pc=np[2]; pd=np[3]; off = kt * 16; }
        else        { pa=ap[0]; pb=ap[1]; pc=ap[2]; pd=ap[3]; off = (kt - 4) * 16; }
        off += 2 * q;

        uint32_t ah0[4], al0[4], ah1[4], al1[4];
        load_split(pa, off, ah0[0], ah0[2], al0[0], al0[2]);
        load_split(pb, off, ah0[1], ah0[3], al0[1], al0[3]);
        load_split(pc, off, ah1[0], ah1[2], al1[0], al1[2]);
        load_split(pd, off, ah1[1], ah1[3], al1[1], al1[3]);

        const uint4* Bp = B16 + (kt * 4 + q) * 96 + gsw;
        #pragma unroll
        for (int nt = 0; nt < 12; nt++) {
            uint4 Bv = Bp[nt * 8];
            mma_bf16(c0[nt], ah0, Bv.x, Bv.y);
            mma_bf16(c0[nt], al0, Bv.x, Bv.y);
            mma_bf16(c0[nt], ah0, Bv.z, Bv.w);
            mma_bf16(c1[nt], ah1, Bv.x, Bv.y);
            mma_bf16(c1[nt], al1, Bv.x, Bv.y);
            mma_bf16(c1[nt], ah1, Bv.z, Bv.w);
        }
    }

    float sums[4] = {0.f, 0.f, 0.f, 0.f}, sqs[4] = {0.f, 0.f, 0.f, 0.f};
    #pragma unroll
    for (int nt = 0; nt < 12; nt++) {
        const int j = nt * 8 + 2 * q;
        const float bv0 = bm_s[j], bv1 = bm_s[j + 1];
        float v;
        v = fmaxf(c0[nt][0] + bv0, 0.f); c0[nt][0] = v; sums[0] += v; sqs[0] += v * v;
        v = fmaxf(c0[nt][1] + bv1, 0.f); c0[nt][1] = v; sums[0] += v; sqs[0] += v * v;
        v = fmaxf(c0[nt][2] + bv0, 0.f); c0[nt][2] = v; sums[1] += v; sqs[1] += v * v;
        v = fmaxf(c0[nt][3] + bv1, 0.f); c0[nt][3] = v; sums[1] += v; sqs[1] += v * v;
        v = fmaxf(c1[nt][0] + bv0, 0.f); c1[nt][0] = v; sums[2] += v; sqs[2] += v * v;
        v = fmaxf(c1[nt][1] + bv1, 0.f); c1[nt][1] = v; sums[2] += v; sqs[2] += v * v;
        v = fmaxf(c1[nt][2] + bv0, 0.f); c1[nt][2] = v; sums[3] += v; sqs[3] += v * v;
        v = fmaxf(c1[nt][3] + bv1, 0.f); c1[nt][3] = v; sums[3] += v; sqs[3] += v * v;
    }
    #pragma unroll
    for (int m = 1; m < 4; m <<= 1) {
        #pragma unroll
        for (int rr = 0; rr < 4; rr++) {
            sums[rr] += __shfl_xor_sync(0xffffffffu, sums[rr], m);
            sqs[rr]  += __shfl_xor_sync(0xffffffffu, sqs[rr],  m);
        }
    }
    if (q == 0) {
        const int rws[4] = {r0, r1, r2, r3};
        #pragma unroll
        for (int rr = 0; rr < 4; rr++) {
            float mean = sums[rr] * (1.f / FIL);
            float var  = sqs[rr] * (1.f / FIL) - mean * mean;
            mn_s[rws[rr]] = mean;
            rs_s[rws[rr]] = rsqrtf(var + LN_EPS);
        }
    }
    __syncthreads();

    #pragma unroll
    for (int nt = 0; nt < 12; nt++) {
        const int j = nt * 8 + 2 * q;
        *(float2*)(Ms + r0 * MSTR + j) = make_float2(c0[nt][0], c0[nt][1]);
        *(float2*)(Ms + r1 * MSTR + j) = make_float2(c0[nt][2], c0[nt][3]);
        *(float2*)(Ms + r2 * MSTR + j) = make_float2(c1[nt][0], c1[nt][1]);
        *(float2*)(Ms + r3 * MSTR + j) = make_float2(c1[nt][2], c1[nt][3]);
    }
    __syncthreads();

    for (int i = t; i < 128 * 24; i += 128) {
        const int row = i / 24;
        const int c4  = i - row * 24;
        const int j   = c4 * 4;
        const int ge  = blockIdx.x * 128 + row;
        if (ge >= NT) continue;
        const float mean = mn_s[row], rstd = rs_s[row];
        float4 v = *(const float4*)(Ms + row * MSTR + j);
        float4 o;
        o.x = (v.x - mean) * rstd * gm_s[j + 0] + bt_s[j + 0];
        o.y = (v.y - mean) * rstd * gm_s[j + 1] + bt_s[j + 1];
        o.z = (v.z - mean) * rstd * gm_s[j + 2] + bt_s[j + 2];
        o.w = (v.w - mean) * rstd * gm_s[j + 3] + bt_s[j + 3];
        ((float4*)(upd_out + (size_t)ge * FIL))[c4] = o;
    }
}

// ---------------- launch ----------------
extern "C" void kernel_launch(void* const* d_in, const int* in_sizes, int n_in,
                              void* d_out, int out_size) {
    const float* nodes = (const float*)d_in[0];
    const float* ef    = (const float*)d_in[1];
    const int*   edges = (const int*)  d_in[2];
    const float* Wm    = (const float*)d_in[3];
    const float* bm    = (const float*)d_in[4];
    const float* gm_m  = (const float*)d_in[5];
    const float* bt_m  = (const float*)d_in[6];
    const float* Wu    = (const float*)d_in[7];
    const float* bu    = (const float*)d_in[8];
    const float* gm_u  = (const float*)d_in[9];
    const float* bt_u  = (const float*)d_in[10];

    float* out = (float*)d_out;
    float* upd = out;                               // (B, N, FILTERS)
    float* msg = out + (size_t)Bq * Nn * FIL;       // (B, E, FILTERS)

    cudaFuncSetAttribute(edge_kernel_mma, cudaFuncAttributeMaxDynamicSharedMemorySize,
                         E_SMEM_BYTES);
    cudaFuncSetAttribute(node_kernel_mma, cudaFuncAttributeMaxDynamicSharedMemorySize,
                         N_SMEM_BYTES);

    zero_agg_kernel<<<1875, 512>>>();
    edge_kernel_mma<<<(Bq * Ee) / 128, 256, E_SMEM_BYTES>>>(
        nodes, ef, edges, Wm, bm, gm_m, bt_m, msg);
    node_kernel_mma<<<(Bq * Nn + 127) / 128, 128, N_SMEM_BYTES>>>(
        nodes, Wu, bu, gm_u, bt_u, upd);
}

// round 10
// speedup vs baseline: 1.1108x; 1.1108x over previous
#include <cuda_runtime.h>
#include <cstdint>

#define Bq   8
#define Nn   5000
#define Ee   40000
#define Ff   64
#define FEe  16
#define FIL  96
#define DM   144
#define DU   160
#define LN_EPS 1e-3f
#define MSTR 104   // Ms row stride (words) — conflict-free
#define NT   (Bq * Nn)

__device__ __align__(16) float g_agg[(size_t)Bq * Nn * FIL];
__device__ __align__(16) float g_pre[(size_t)Bq * Nn * 192];   // [node][0:96]=src-term, [96:192]=dst-term

// ---------------- helpers ----------------
__device__ __forceinline__ void red4(float* addr, float4 v) {
    asm volatile("red.global.add.v4.f32 [%0], {%1,%2,%3,%4};"
                 :: "l"(addr), "f"(v.x), "f"(v.y), "f"(v.z), "f"(v.w) : "memory");
}
// split (x,y) fp32 pair into bf16x2 hi + bf16x2 lo (lo = residual)
__device__ __forceinline__ uint32_t split_pair(float x, float y, uint32_t& lo2) {
    uint32_t h;
    asm("cvt.rn.bf16x2.f32 %0, %1, %2;" : "=r"(h) : "f"(y), "f"(x));
    float hx = __uint_as_float(h << 16);
    float hy = __uint_as_float(h & 0xffff0000u);
    float rx = x - hx, ry = y - hy;
    asm("cvt.rn.bf16x2.f32 %0, %1, %2;" : "=r"(lo2) : "f"(ry), "f"(rx));
    return h;
}
__device__ __forceinline__ void mma_bf16(float* c, const uint32_t* a,
                                         uint32_t b0, uint32_t b1) {
    asm volatile(
        "mma.sync.aligned.m16n8k16.row.col.f32.bf16.bf16.f32 "
        "{%0,%1,%2,%3}, {%4,%5,%6,%7}, {%8,%9}, {%0,%1,%2,%3};"
        : "+f"(c[0]), "+f"(c[1]), "+f"(c[2]), "+f"(c[3])
        : "r"(a[0]), "r"(a[1]), "r"(a[2]), "r"(a[3]), "r"(b0), "r"(b1));
}
__device__ __forceinline__ void load_split(const float* p, int off,
                                           uint32_t& h0, uint32_t& h2,
                                           uint32_t& l0, uint32_t& l2) {
    float2 x0 = *(const float2*)(p + off);
    float2 x2 = *(const float2*)(p + off + 8);
    h0 = split_pair(x0.x, x0.y, l0);
    h2 = split_pair(x2.x, x2.y, l2);
}

// ================= pre kernel =================
// g_pre[row][0:192] = nodes[row] @ [Wm(0:64) | Wm(64:128)]  (no bias/relu)
// Also zeroes g_agg. 128 rows/block, 8 warps x 16 rows, K=64 (4 k-steps), N=192.
#define P_SMEM_BYTES (16 * 192 * 16)   // 3072 uint4 = 48 KB

__global__ void __launch_bounds__(256) pre_kernel(
    const float* __restrict__ nodes, const float* __restrict__ Wm)
{
    extern __shared__ float sm[];
    uint4* B16 = (uint4*)sm;
    const int t = threadIdx.x;

    // zero g_agg (grid-stride; 313 blocks cover it in ~12 iters/thread)
    {
        const int nblk = gridDim.x;
        float4* p = (float4*)g_agg;
        for (size_t i = (size_t)blockIdx.x * 256 + t; i < (size_t)NT * FIL / 4;
             i += (size_t)nblk * 256)
            p[i] = make_float4(0.f, 0.f, 0.f, 0.f);
    }

    // stage combined weights (64 x 192) as paired hi/lo uint4
    for (int i = t; i < 16 * 192; i += 256) {
        int slot = i / 192, n = i - slot * 192;
        int kt = slot >> 2, qs = slot & 3;
        int ka = (kt * 8 + qs) * 2;        // k rows: ka, ka+1 (0..63)
        int kb = ka + 8;                   // k rows: kb, kb+1
        const int col = (n < 96) ? n : (n - 96);
        const int ro  = (n < 96) ? 0 : 64;
        float w0a = Wm[(ro + ka) * FIL + col],     w1a = Wm[(ro + ka + 1) * FIL + col];
        float w0b = Wm[(ro + kb) * FIL + col],     w1b = Wm[(ro + kb + 1) * FIL + col];
        uint32_t la, lb;
        uint32_t ha = split_pair(w0a, w1a, la);
        uint32_t hb = split_pair(w0b, w1b, lb);
        B16[slot * 192 + (n ^ (2 * qs))] = make_uint4(ha, hb, la, lb);
    }
    __syncthreads();

    const int lane = t & 31;
    const int w    = t >> 5;
    const int g    = lane >> 2;
    const int q    = lane & 3;
    const int r0 = w * 16 + g, r1 = r0 + 8;
    const int gn0 = blockIdx.x * 128 + r0;
    const int gn1 = gn0 + 8;
    const int g0c = gn0 < NT ? gn0 : NT - 1;
    const int g1c = gn1 < NT ? gn1 : NT - 1;
    const float* n0 = nodes + (size_t)g0c * Ff;
    const float* n1 = nodes + (size_t)g1c * Ff;

    float c[24][4];
    #pragma unroll
    for (int nt = 0; nt < 24; nt++) { c[nt][0]=0.f; c[nt][1]=0.f; c[nt][2]=0.f; c[nt][3]=0.f; }

    const int gsw = g ^ (2 * q);
    const int qo  = 2 * q;

    #pragma unroll
    for (int kt = 0; kt < 4; kt++) {
        uint32_t ah[4], al[4];
        load_split(n0, kt * 16 + qo, ah[0], ah[2], al[0], al[2]);
        load_split(n1, kt * 16 + qo, ah[1], ah[3], al[1], al[3]);
        const uint4* Bp = B16 + (kt * 4 + q) * 192 + gsw;
        #pragma unroll
        for (int nt = 0; nt < 24; nt++) {
            uint4 Bv = Bp[nt * 8];
            mma_bf16(c[nt], ah, Bv.x, Bv.y);
            mma_bf16(c[nt], al, Bv.x, Bv.y);
            mma_bf16(c[nt], ah, Bv.z, Bv.w);
        }
    }

    if (gn0 < NT) {
        float* o = g_pre + (size_t)gn0 * 192 + qo;
        #pragma unroll
        for (int nt = 0; nt < 24; nt++)
            *(float2*)(o + nt * 8) = make_float2(c[nt][0], c[nt][1]);
    }
    if (gn1 < NT) {
        float* o = g_pre + (size_t)gn1 * 192 + qo;
        #pragma unroll
        for (int nt = 0; nt < 24; nt++)
            *(float2*)(o + nt * 8) = make_float2(c[nt][2], c[nt][3]);
    }
}

// ================= edge kernel =================
// 128 edges/block. Tensor part: only ef @ Wm[128:144] (1 k-step).
// Then v = efc + g_pre[src][j] + g_pre[dst][96+j] + bias -> relu -> LN.
#define XS_MS    0             // 128 x 104 = 13312 words (B16ef 1536 words overlays start)
#define XS_BM    13312
#define XS_GM    13408
#define XS_BT    13504
#define XS_SEB   13600         // 128 int2 = 256 words
#define XS_TOTAL 13856
#define E_SMEM_BYTES (XS_TOTAL * 4)

__global__ void __launch_bounds__(256) edge_kernel_mma(
    const float* __restrict__ ef,    const int*   __restrict__ edges,
    const float* __restrict__ Wm,    const float* __restrict__ bm,
    const float* __restrict__ gm,    const float* __restrict__ bt,
    float* __restrict__ msg_out)
{
    extern __shared__ float sm[];
    uint4* B16  = (uint4*)sm;         // 4 slots x 96 uint4 (dead after MMA)
    float* Ms   = sm + XS_MS;         // overlay, stride MSTR
    float* bm_s = sm + XS_BM;
    float* gm_s = sm + XS_GM;
    float* bt_s = sm + XS_BT;
    int2*  seb  = (int2*)(sm + XS_SEB);

    const int t = threadIdx.x;

    // stage ef-weights Wm[128:144] as paired hi/lo uint4
    for (int i = t; i < 4 * 96; i += 256) {
        int qs = i / 96, n = i - qs * 96;
        uint32_t la, lb;
        uint32_t ha = split_pair(Wm[(128 + 2 * qs) * FIL + n],
                                 Wm[(129 + 2 * qs) * FIL + n], la);
        uint32_t hb = split_pair(Wm[(136 + 2 * qs) * FIL + n],
                                 Wm[(137 + 2 * qs) * FIL + n], lb);
        B16[qs * 96 + (n ^ (2 * qs))] = make_uint4(ha, hb, la, lb);
    }
    if (t < FIL) { bm_s[t] = bm[t]; gm_s[t] = gm[t]; bt_s[t] = bt[t]; }
    if (t < 128) seb[t] = ((const int2*)edges)[blockIdx.x * 128 + t];
    __syncthreads();

    const int lane = t & 31;
    const int w    = t >> 5;
    const int g    = lane >> 2;
    const int q    = lane & 3;
    const int r0 = w * 16 + g, r1 = r0 + 8;
    const int ge0 = blockIdx.x * 128 + r0;
    const int ge1 = ge0 + 8;
    const int b0 = ge0 / Ee, b1 = ge1 / Ee;
    const int2 e0 = seb[r0], e1 = seb[r1];
    const int gsw = g ^ (2 * q);
    const int qo  = 2 * q;

    // ---- ef GEMM: single k-step, 3 terms ----
    float c[12][4];
    #pragma unroll
    for (int nt = 0; nt < 12; nt++) { c[nt][0]=0.f; c[nt][1]=0.f; c[nt][2]=0.f; c[nt][3]=0.f; }
    {
        uint32_t ah[4], al[4];
        load_split(ef + (size_t)ge0 * FEe, qo, ah[0], ah[2], al[0], al[2]);
        load_split(ef + (size_t)ge1 * FEe, qo, ah[1], ah[3], al[1], al[3]);
        const uint4* Bp = B16 + q * 96 + gsw;
        #pragma unroll
        for (int nt = 0; nt < 12; nt++) {
            uint4 Bv = Bp[nt * 8];
            mma_bf16(c[nt], ah, Bv.x, Bv.y);
            mma_bf16(c[nt], al, Bv.x, Bv.y);
            mma_bf16(c[nt], ah, Bv.z, Bv.w);
        }
    }

    // ---- gather g_pre terms + bias + relu + LN stats ----
    const float* pA = g_pre + (size_t)(b0 * Nn + e0.x) * 192;        // src0 term
    const float* pB = g_pre + (size_t)(b0 * Nn + e0.y) * 192 + 96;   // dst0 term
    const float* pC = g_pre + (size_t)(b1 * Nn + e1.x) * 192;
    const float* pD = g_pre + (size_t)(b1 * Nn + e1.y) * 192 + 96;

    float sum0 = 0.f, sq0 = 0.f, sum1 = 0.f, sq1 = 0.f;
    #pragma unroll
    for (int nt = 0; nt < 12; nt++) {
        const int j = nt * 8 + qo;
        float2 xa = *(const float2*)(pA + j);
        float2 xb = *(const float2*)(pB + j);
        float2 xc = *(const float2*)(pC + j);
        float2 xd = *(const float2*)(pD + j);
        const float bv0 = bm_s[j], bv1 = bm_s[j + 1];
        float v0 = fmaxf(c[nt][0] + xa.x + xb.x + bv0, 0.f);
        float v1 = fmaxf(c[nt][1] + xa.y + xb.y + bv1, 0.f);
        float v2 = fmaxf(c[nt][2] + xc.x + xd.x + bv0, 0.f);
        float v3 = fmaxf(c[nt][3] + xc.y + xd.y + bv1, 0.f);
        c[nt][0] = v0; c[nt][1] = v1; c[nt][2] = v2; c[nt][3] = v3;
        sum0 += v0 + v1;  sq0 += v0 * v0 + v1 * v1;
        sum1 += v2 + v3;  sq1 += v2 * v2 + v3 * v3;
    }
    #pragma unroll
    for (int m = 1; m < 4; m <<= 1) {
        sum0 += __shfl_xor_sync(0xffffffffu, sum0, m);
        sq0  += __shfl_xor_sync(0xffffffffu, sq0,  m);
        sum1 += __shfl_xor_sync(0xffffffffu, sum1, m);
        sq1  += __shfl_xor_sync(0xffffffffu, sq1,  m);
    }
    const float mean0 = sum0 * (1.f / FIL);
    const float rstd0 = rsqrtf(sq0 * (1.f / FIL) - mean0 * mean0 + LN_EPS);
    const float mean1 = sum1 * (1.f / FIL);
    const float rstd1 = rsqrtf(sq1 * (1.f / FIL) - mean1 * mean1 + LN_EPS);

    __syncthreads();   // B16 dead -> overlay Ms

    // ---- apply LN, stage final messages ----
    #pragma unroll
    for (int nt = 0; nt < 12; nt++) {
        const int j = nt * 8 + qo;
        const float g0 = gm_s[j], g1 = gm_s[j + 1];
        const float t0 = bt_s[j], t1 = bt_s[j + 1];
        *(float2*)(Ms + r0 * MSTR + j) = make_float2(
            (c[nt][0] - mean0) * rstd0 * g0 + t0,
            (c[nt][1] - mean0) * rstd0 * g1 + t1);
        *(float2*)(Ms + r1 * MSTR + j) = make_float2(
            (c[nt][2] - mean1) * rstd1 * g0 + t0,
            (c[nt][3] - mean1) * rstd1 * g1 + t1);
    }
    __syncthreads();

    // ---- coalesced store + vector atomics ----
    for (int i = t; i < 128 * 24; i += 256) {
        const int row = i / 24;
        const int c4  = i - row * 24;
        const int j   = c4 * 4;
        float4 o = *(const float4*)(Ms + row * MSTR + j);
        const int ge = blockIdx.x * 128 + row;
        const int b  = ge / Ee;
        ((float4*)(msg_out + (size_t)ge * FIL))[c4] = o;
        red4(g_agg + ((size_t)b * Nn + seb[row].y) * FIL + j, o);
    }
}

// ================= node kernel (unchanged, passing) =================
#define NS_B16   0            // 40*96 uint4 = 15360 words
#define NS_BM    15360
#define NS_GM    15456
#define NS_BT    15552
#define NS_MEAN  15648
#define NS_RSTD  15776
#define NS_TOTAL 15904
#define N_SMEM_BYTES (NS_TOTAL * 4)

__global__ void __launch_bounds__(128) node_kernel_mma(
    const float* __restrict__ nodes, const float* __restrict__ Wu,
    const float* __restrict__ bu,    const float* __restrict__ gm,
    const float* __restrict__ bt,    float* __restrict__ upd_out)
{
    extern __shared__ float sm[];
    uint4* B16  = (uint4*)sm;
    float* Ms   = sm;
    float* bm_s = sm + NS_BM;
    float* gm_s = sm + NS_GM;
    float* bt_s = sm + NS_BT;
    float* mn_s = sm + NS_MEAN;
    float* rs_s = sm + NS_RSTD;

    const int t = threadIdx.x;

    for (int i = t; i < 40 * 96; i += 128) {
        int slot = i / 96, n = i - slot * 96;
        int kt = slot >> 2, q = slot & 3;
        int k2a = kt * 8 + q, k2b = k2a + 4;
        uint32_t la, lb;
        uint32_t ha = split_pair(Wu[(2 * k2a) * FIL + n], Wu[(2 * k2a + 1) * FIL + n], la);
        uint32_t hb = split_pair(Wu[(2 * k2b) * FIL + n], Wu[(2 * k2b + 1) * FIL + n], lb);
        B16[slot * 96 + (n ^ (2 * q))] = make_uint4(ha, hb, la, lb);
    }
    if (t < FIL) { bm_s[t] = bu[t]; gm_s[t] = gm[t]; bt_s[t] = bt[t]; }
    __syncthreads();

    const int lane = t & 31;
    const int w    = t >> 5;
    const int g    = lane >> 2;
    const int q    = lane & 3;
    const int r0 = w * 32 + g, r1 = r0 + 8, r2 = r0 + 16, r3 = r0 + 24;

    int gn[4] = {blockIdx.x * 128 + r0, blockIdx.x * 128 + r1,
                 blockIdx.x * 128 + r2, blockIdx.x * 128 + r3};
    const float* np[4];
    const float* ap[4];
    #pragma unroll
    for (int rr = 0; rr < 4; rr++) {
        int gc = gn[rr] < NT ? gn[rr] : NT - 1;
        np[rr] = nodes + (size_t)gc * Ff;
        ap[rr] = g_agg + (size_t)gc * FIL;
    }

    float c0[12][4], c1[12][4];
    #pragma unroll
    for (int nt = 0; nt < 12; nt++) {
        c0[nt][0]=0.f; c0[nt][1]=0.f; c0[nt][2]=0.f; c0[nt][3]=0.f;
        c1[nt][0]=0.f; c1[nt][1]=0.f; c1[nt][2]=0.f; c1[nt][3]=0.f;
    }
    const int gsw = g ^ (2 * q);

    #pragma unroll
    for (int kt = 0; kt < 10; kt++) {
        const float *pa, *pb, *pc, *pd;
        int off;
        if (kt < 4) { pa=np[0]; pb=np[1]; pc=np[2]; pd=np[3]; off = kt * 16; }
        else        { pa=ap[0]; pb=ap[1]; pc=ap[2]; pd=ap[3]; off = (kt - 4) * 16; }
        off += 2 * q;

        uint32_t ah0[4], al0[4], ah1[4], al1[4];
        load_split(pa, off, ah0[0], ah0[2], al0[0], al0[2]);
        load_split(pb, off, ah0[1], ah0[3], al0[1], al0[3]);
        load_split(pc, off, ah1[0], ah1[2], al1[0], al1[2]);
        load_split(pd, off, ah1[1], ah1[3], al1[1], al1[3]);

        const uint4* Bp = B16 + (kt * 4 + q) * 96 + gsw;
        #pragma unroll
        for (int nt = 0; nt < 12; nt++) {
            uint4 Bv = Bp[nt * 8];
            mma_bf16(c0[nt], ah0, Bv.x, Bv.y);
            mma_bf16(c0[nt], al0, Bv.x, Bv.y);
            mma_bf16(c0[nt], ah0, Bv.z, Bv.w);
            mma_bf16(c1[nt], ah1, Bv.x, Bv.y);
            mma_bf16(c1[nt], al1, Bv.x, Bv.y);
            mma_bf16(c1[nt], ah1, Bv.z, Bv.w);
        }
    }

    float sums[4] = {0.f, 0.f, 0.f, 0.f}, sqs[4] = {0.f, 0.f, 0.f, 0.f};
    #pragma unroll
    for (int nt = 0; nt < 12; nt++) {
        const int j = nt * 8 + 2 * q;
        const float bv0 = bm_s[j], bv1 = bm_s[j + 1];
        float v;
        v = fmaxf(c0[nt][0] + bv0, 0.f); c0[nt][0] = v; sums[0] += v; sqs[0] += v * v;
        v = fmaxf(c0[nt][1] + bv1, 0.f); c0[nt][1] = v; sums[0] += v; sqs[0] += v * v;
        v = fmaxf(c0[nt][2] + bv0, 0.f); c0[nt][2] = v; sums[1] += v; sqs[1] += v * v;
        v = fmaxf(c0[nt][3] + bv1, 0.f); c0[nt][3] = v; sums[1] += v; sqs[1] += v * v;
        v = fmaxf(c1[nt][0] + bv0, 0.f); c1[nt][0] = v; sums[2] += v; sqs[2] += v * v;
        v = fmaxf(c1[nt][1] + bv1, 0.f); c1[nt][1] = v; sums[2] += v; sqs[2] += v * v;
        v = fmaxf(c1[nt][2] + bv0, 0.f); c1[nt][2] = v; sums[3] += v; sqs[3] += v * v;
        v = fmaxf(c1[nt][3] + bv1, 0.f); c1[nt][3] = v; sums[3] += v; sqs[3] += v * v;
    }
    #pragma unroll
    for (int m = 1; m < 4; m <<= 1) {
        #pragma unroll
        for (int rr = 0; rr < 4; rr++) {
            sums[rr] += __shfl_xor_sync(0xffffffffu, sums[rr], m);
            sqs[rr]  += __shfl_xor_sync(0xffffffffu, sqs[rr],  m);
        }
    }
    if (q == 0) {
        const int rws[4] = {r0, r1, r2, r3};
        #pragma unroll
        for (int rr = 0; rr < 4; rr++) {
            float mean = sums[rr] * (1.f / FIL);
            float var  = sqs[rr] * (1.f / FIL) - mean * mean;
            mn_s[rws[rr]] = mean;
            rs_s[rws[rr]] = rsqrtf(var + LN_EPS);
        }
    }
    __syncthreads();

    #pragma unroll
    for (int nt = 0; nt < 12; nt++) {
        const int j = nt * 8 + 2 * q;
        *(float2*)(Ms + r0 * MSTR + j) = make_float2(c0[nt][0], c0[nt][1]);
        *(float2*)(Ms + r1 * MSTR + j) = make_float2(c0[nt][2], c0[nt][3]);
        *(float2*)(Ms + r2 * MSTR + j) = make_float2(c1[nt][0], c1[nt][1]);
        *(float2*)(Ms + r3 * MSTR + j) = make_float2(c1[nt][2], c1[nt][3]);
    }
    __syncthreads();

    for (int i = t; i < 128 * 24; i += 128) {
        const int row = i / 24;
        const int c4  = i - row * 24;
        const int j   = c4 * 4;
        const int ge  = blockIdx.x * 128 + row;
        if (ge >= NT) continue;
        const float mean = mn_s[row], rstd = rs_s[row];
        float4 v = *(const float4*)(Ms + row * MSTR + j);
        float4 o;
        o.x = (v.x - mean) * rstd * gm_s[j + 0] + bt_s[j + 0];
        o.y = (v.y - mean) * rstd * gm_s[j + 1] + bt_s[j + 1];
        o.z = (v.z - mean) * rstd * gm_s[j + 2] + bt_s[j + 2];
        o.w = (v.w - mean) * rstd * gm_s[j + 3] + bt_s[j + 3];
        ((float4*)(upd_out + (size_t)ge * FIL))[c4] = o;
    }
}

// ---------------- launch ----------------
extern "C" void kernel_launch(void* const* d_in, const int* in_sizes, int n_in,
                              void* d_out, int out_size) {
    const float* nodes = (const float*)d_in[0];
    const float* ef    = (const float*)d_in[1];
    const int*   edges = (const int*)  d_in[2];
    const float* Wm    = (const float*)d_in[3];
    const float* bm    = (const float*)d_in[4];
    const float* gm_m  = (const float*)d_in[5];
    const float* bt_m  = (const float*)d_in[6];
    const float* Wu    = (const float*)d_in[7];
    const float* bu    = (const float*)d_in[8];
    const float* gm_u  = (const float*)d_in[9];
    const float* bt_u  = (const float*)d_in[10];

    float* out = (float*)d_out;
    float* upd = out;                               // (B, N, FILTERS)
    float* msg = out + (size_t)Bq * Nn * FIL;       // (B, E, FILTERS)

    cudaFuncSetAttribute(pre_kernel, cudaFuncAttributeMaxDynamicSharedMemorySize,
                         P_SMEM_BYTES);
    cudaFuncSetAttribute(edge_kernel_mma, cudaFuncAttributeMaxDynamicSharedMemorySize,
                         E_SMEM_BYTES);
    cudaFuncSetAttribute(node_kernel_mma, cudaFuncAttributeMaxDynamicSharedMemorySize,
                         N_SMEM_BYTES);

    pre_kernel<<<(NT + 127) / 128, 256, P_SMEM_BYTES>>>(nodes, Wm);
    edge_kernel_mma<<<(Bq * Ee) / 128, 256, E_SMEM_BYTES>>>(
        ef, edges, Wm, bm, gm_m, bt_m, msg);
    node_kernel_mma<<<(NT + 127) / 128, 128, N_SMEM_BYTES>>>(
        nodes, Wu, bu, gm_u, bt_u, upd);
}

// round 11
// speedup vs baseline: 1.1472x; 1.0328x over previous
#include <cuda_runtime.h>
#include <cstdint>

#define Bq   8
#define Nn   5000
#define Ee   40000
#define Ff   64
#define FEe  16
#define FIL  96
#define DM   144
#define DU   160
#define LN_EPS 1e-3f
#define MSTR 104   // Ms row stride (words) — conflict-free
#define NT   (Bq * Nn)

__device__ __align__(16) float g_agg[(size_t)Bq * Nn * FIL];
__device__ __align__(16) float g_pre[(size_t)Bq * Nn * 192];   // [node][0:96]=src-term, [96:192]=dst-term

// ---------------- helpers ----------------
__device__ __forceinline__ void red4(float* addr, float4 v) {
    asm volatile("red.global.add.v4.f32 [%0], {%1,%2,%3,%4};"
                 :: "l"(addr), "f"(v.x), "f"(v.y), "f"(v.z), "f"(v.w) : "memory");
}
// split (x,y) fp32 pair into bf16x2 hi + bf16x2 lo (lo = residual)
__device__ __forceinline__ uint32_t split_pair(float x, float y, uint32_t& lo2) {
    uint32_t h;
    asm("cvt.rn.bf16x2.f32 %0, %1, %2;" : "=r"(h) : "f"(y), "f"(x));
    float hx = __uint_as_float(h << 16);
    float hy = __uint_as_float(h & 0xffff0000u);
    float rx = x - hx, ry = y - hy;
    asm("cvt.rn.bf16x2.f32 %0, %1, %2;" : "=r"(lo2) : "f"(ry), "f"(rx));
    return h;
}
__device__ __forceinline__ void mma_bf16(float* c, const uint32_t* a,
                                         uint32_t b0, uint32_t b1) {
    asm volatile(
        "mma.sync.aligned.m16n8k16.row.col.f32.bf16.bf16.f32 "
        "{%0,%1,%2,%3}, {%4,%5,%6,%7}, {%8,%9}, {%0,%1,%2,%3};"
        : "+f"(c[0]), "+f"(c[1]), "+f"(c[2]), "+f"(c[3])
        : "r"(a[0]), "r"(a[1]), "r"(a[2]), "r"(a[3]), "r"(b0), "r"(b1));
}
__device__ __forceinline__ void load_split(const float* p, int off,
                                           uint32_t& h0, uint32_t& h2,
                                           uint32_t& l0, uint32_t& l2) {
    float2 x0 = *(const float2*)(p + off);
    float2 x2 = *(const float2*)(p + off + 8);
    h0 = split_pair(x0.x, x0.y, l0);
    h2 = split_pair(x2.x, x2.y, l2);
}

// ================= pre kernel =================
// g_pre[row][0:192] = nodes[row] @ [Wm(0:64) | Wm(64:128)]  (no bias/relu)
// Also zeroes g_agg. 128 rows/block, 8 warps x 16 rows, K=64 (4 k-steps), N=192.
#define P_SMEM_BYTES (16 * 192 * 16)   // 3072 uint4 = 48 KB

__global__ void __launch_bounds__(256, 2) pre_kernel(
    const float* __restrict__ nodes, const float* __restrict__ Wm)
{
    extern __shared__ float sm[];
    uint4* B16 = (uint4*)sm;
    const int t = threadIdx.x;

    // zero g_agg (grid-stride)
    {
        const int nblk = gridDim.x;
        float4* p = (float4*)g_agg;
        for (size_t i = (size_t)blockIdx.x * 256 + t; i < (size_t)NT * FIL / 4;
             i += (size_t)nblk * 256)
            p[i] = make_float4(0.f, 0.f, 0.f, 0.f);
    }

    // stage combined weights (64 x 192) as paired hi/lo uint4
    for (int i = t; i < 16 * 192; i += 256) {
        int slot = i / 192, n = i - slot * 192;
        int kt = slot >> 2, qs = slot & 3;
        int ka = (kt * 8 + qs) * 2;
        int kb = ka + 8;
        const int col = (n < 96) ? n : (n - 96);
        const int ro  = (n < 96) ? 0 : 64;
        float w0a = Wm[(ro + ka) * FIL + col],     w1a = Wm[(ro + ka + 1) * FIL + col];
        float w0b = Wm[(ro + kb) * FIL + col],     w1b = Wm[(ro + kb + 1) * FIL + col];
        uint32_t la, lb;
        uint32_t ha = split_pair(w0a, w1a, la);
        uint32_t hb = split_pair(w0b, w1b, lb);
        B16[slot * 192 + (n ^ (2 * qs))] = make_uint4(ha, hb, la, lb);
    }
    __syncthreads();

    const int lane = t & 31;
    const int w    = t >> 5;
    const int g    = lane >> 2;
    const int q    = lane & 3;
    const int r0 = w * 16 + g, r1 = r0 + 8;
    const int gn0 = blockIdx.x * 128 + r0;
    const int gn1 = gn0 + 8;
    const int g0c = gn0 < NT ? gn0 : NT - 1;
    const int g1c = gn1 < NT ? gn1 : NT - 1;
    const float* n0 = nodes + (size_t)g0c * Ff;
    const float* n1 = nodes + (size_t)g1c * Ff;

    float c[24][4];
    #pragma unroll
    for (int nt = 0; nt < 24; nt++) { c[nt][0]=0.f; c[nt][1]=0.f; c[nt][2]=0.f; c[nt][3]=0.f; }

    const int gsw = g ^ (2 * q);
    const int qo  = 2 * q;

    #pragma unroll
    for (int kt = 0; kt < 4; kt++) {
        uint32_t ah[4], al[4];
        load_split(n0, kt * 16 + qo, ah[0], ah[2], al[0], al[2]);
        load_split(n1, kt * 16 + qo, ah[1], ah[3], al[1], al[3]);
        const uint4* Bp = B16 + (kt * 4 + q) * 192 + gsw;
        #pragma unroll
        for (int nt = 0; nt < 24; nt++) {
            uint4 Bv = Bp[nt * 8];
            mma_bf16(c[nt], ah, Bv.x, Bv.y);
            mma_bf16(c[nt], al, Bv.x, Bv.y);
            mma_bf16(c[nt], ah, Bv.z, Bv.w);
        }
    }

    if (gn0 < NT) {
        float* o = g_pre + (size_t)gn0 * 192 + qo;
        #pragma unroll
        for (int nt = 0; nt < 24; nt++)
            *(float2*)(o + nt * 8) = make_float2(c[nt][0], c[nt][1]);
    }
    if (gn1 < NT) {
        float* o = g_pre + (size_t)gn1 * 192 + qo;
        #pragma unroll
        for (int nt = 0; nt < 24; nt++)
            *(float2*)(o + nt * 8) = make_float2(c[nt][2], c[nt][3]);
    }
}

// ================= edge kernel =================
// 128 edges/block. c init = g_pre[src] + g_pre[dst] + bias (loads issue first),
// then ef @ Wm[128:144] accumulates via MMA (1 k-step), relu + LN, store + red4.
#define XS_MS    0             // 128 x 104 = 13312 words (B16ef 1536 words overlays start)
#define XS_BM    13312
#define XS_GM    13408
#define XS_BT    13504
#define XS_SEB   13600         // 128 int2 = 256 words
#define XS_TOTAL 13856
#define E_SMEM_BYTES (XS_TOTAL * 4)

__global__ void __launch_bounds__(256, 3) edge_kernel_mma(
    const float* __restrict__ ef,    const int*   __restrict__ edges,
    const float* __restrict__ Wm,    const float* __restrict__ bm,
    const float* __restrict__ gm,    const float* __restrict__ bt,
    float* __restrict__ msg_out)
{
    extern __shared__ float sm[];
    uint4* B16  = (uint4*)sm;         // 4 slots x 96 uint4 (dead after MMA)
    float* Ms   = sm + XS_MS;         // overlay, stride MSTR
    float* bm_s = sm + XS_BM;
    float* gm_s = sm + XS_GM;
    float* bt_s = sm + XS_BT;
    int2*  seb  = (int2*)(sm + XS_SEB);

    const int t = threadIdx.x;

    // stage ef-weights Wm[128:144] as paired hi/lo uint4
    for (int i = t; i < 4 * 96; i += 256) {
        int qs = i / 96, n = i - qs * 96;
        uint32_t la, lb;
        uint32_t ha = split_pair(Wm[(128 + 2 * qs) * FIL + n],
                                 Wm[(129 + 2 * qs) * FIL + n], la);
        uint32_t hb = split_pair(Wm[(136 + 2 * qs) * FIL + n],
                                 Wm[(137 + 2 * qs) * FIL + n], lb);
        B16[qs * 96 + (n ^ (2 * qs))] = make_uint4(ha, hb, la, lb);
    }
    if (t < FIL) { bm_s[t] = bm[t]; gm_s[t] = gm[t]; bt_s[t] = bt[t]; }
    if (t < 128) seb[t] = ((const int2*)edges)[blockIdx.x * 128 + t];
    __syncthreads();

    const int lane = t & 31;
    const int w    = t >> 5;
    const int g    = lane >> 2;
    const int q    = lane & 3;
    const int r0 = w * 16 + g, r1 = r0 + 8;
    const int ge0 = blockIdx.x * 128 + r0;
    const int ge1 = ge0 + 8;
    const int b0 = ge0 / Ee, b1 = ge1 / Ee;
    const int2 e0 = seb[r0], e1 = seb[r1];
    const int gsw = g ^ (2 * q);
    const int qo  = 2 * q;

    // ---- init accumulators with gathered g_pre terms + bias (loads lead) ----
    const float* pA = g_pre + (size_t)(b0 * Nn + e0.x) * 192;        // src0 term
    const float* pB = g_pre + (size_t)(b0 * Nn + e0.y) * 192 + 96;   // dst0 term
    const float* pC = g_pre + (size_t)(b1 * Nn + e1.x) * 192;
    const float* pD = g_pre + (size_t)(b1 * Nn + e1.y) * 192 + 96;

    float c[12][4];
    #pragma unroll
    for (int nt = 0; nt < 12; nt++) {
        const int j = nt * 8 + qo;
        float2 xa = *(const float2*)(pA + j);
        float2 xb = *(const float2*)(pB + j);
        float2 xc = *(const float2*)(pC + j);
        float2 xd = *(const float2*)(pD + j);
        const float bv0 = bm_s[j], bv1 = bm_s[j + 1];
        c[nt][0] = xa.x + xb.x + bv0;
        c[nt][1] = xa.y + xb.y + bv1;
        c[nt][2] = xc.x + xd.x + bv0;
        c[nt][3] = xc.y + xd.y + bv1;
    }

    // ---- ef GEMM accumulates on top: single k-step, 3 terms ----
    {
        uint32_t ah[4], al[4];
        load_split(ef + (size_t)ge0 * FEe, qo, ah[0], ah[2], al[0], al[2]);
        load_split(ef + (size_t)ge1 * FEe, qo, ah[1], ah[3], al[1], al[3]);
        const uint4* Bp = B16 + q * 96 + gsw;
        #pragma unroll
        for (int nt = 0; nt < 12; nt++) {
            uint4 Bv = Bp[nt * 8];
            mma_bf16(c[nt], ah, Bv.x, Bv.y);
            mma_bf16(c[nt], al, Bv.x, Bv.y);
            mma_bf16(c[nt], ah, Bv.z, Bv.w);
        }
    }

    // ---- relu + LN stats ----
    float sum0 = 0.f, sq0 = 0.f, sum1 = 0.f, sq1 = 0.f;
    #pragma unroll
    for (int nt = 0; nt < 12; nt++) {
        float v0 = fmaxf(c[nt][0], 0.f);
        float v1 = fmaxf(c[nt][1], 0.f);
        float v2 = fmaxf(c[nt][2], 0.f);
        float v3 = fmaxf(c[nt][3], 0.f);
        c[nt][0] = v0; c[nt][1] = v1; c[nt][2] = v2; c[nt][3] = v3;
        sum0 += v0 + v1;  sq0 += v0 * v0 + v1 * v1;
        sum1 += v2 + v3;  sq1 += v2 * v2 + v3 * v3;
    }
    #pragma unroll
    for (int m = 1; m < 4; m <<= 1) {
        sum0 += __shfl_xor_sync(0xffffffffu, sum0, m);
        sq0  += __shfl_xor_sync(0xffffffffu, sq0,  m);
        sum1 += __shfl_xor_sync(0xffffffffu, sum1, m);
        sq1  += __shfl_xor_sync(0xffffffffu, sq1,  m);
    }
    const float mean0 = sum0 * (1.f / FIL);
    const float rstd0 = rsqrtf(sq0 * (1.f / FIL) - mean0 * mean0 + LN_EPS);
    const float mean1 = sum1 * (1.f / FIL);
    const float rstd1 = rsqrtf(sq1 * (1.f / FIL) - mean1 * mean1 + LN_EPS);

    __syncthreads();   // B16 dead -> overlay Ms

    // ---- apply LN, stage final messages ----
    #pragma unroll
    for (int nt = 0; nt < 12; nt++) {
        const int j = nt * 8 + qo;
        const float g0 = gm_s[j], g1 = gm_s[j + 1];
        const float t0 = bt_s[j], t1 = bt_s[j + 1];
        *(float2*)(Ms + r0 * MSTR + j) = make_float2(
            (c[nt][0] - mean0) * rstd0 * g0 + t0,
            (c[nt][1] - mean0) * rstd0 * g1 + t1);
        *(float2*)(Ms + r1 * MSTR + j) = make_float2(
            (c[nt][2] - mean1) * rstd1 * g0 + t0,
            (c[nt][3] - mean1) * rstd1 * g1 + t1);
    }
    __syncthreads();

    // ---- coalesced store + vector atomics ----
    for (int i = t; i < 128 * 24; i += 256) {
        const int row = i / 24;
        const int c4  = i - row * 24;
        const int j   = c4 * 4;
        float4 o = *(const float4*)(Ms + row * MSTR + j);
        const int ge = blockIdx.x * 128 + row;
        const int b  = ge / Ee;
        ((float4*)(msg_out + (size_t)ge * FIL))[c4] = o;
        red4(g_agg + ((size_t)b * Nn + seb[row].y) * FIL + j, o);
    }
}

// ================= node kernel (unchanged, passing) =================
#define NS_B16   0            // 40*96 uint4 = 15360 words
#define NS_BM    15360
#define NS_GM    15456
#define NS_BT    15552
#define NS_MEAN  15648
#define NS_RSTD  15776
#define NS_TOTAL 15904
#define N_SMEM_BYTES (NS_TOTAL * 4)

__global__ void __launch_bounds__(128) node_kernel_mma(
    const float* __restrict__ nodes, const float* __restrict__ Wu,
    const float* __restrict__ bu,    const float* __restrict__ gm,
    const float* __restrict__ bt,    float* __restrict__ upd_out)
{
    extern __shared__ float sm[];
    uint4* B16  = (uint4*)sm;
    float* Ms   = sm;
    float* bm_s = sm + NS_BM;
    float* gm_s = sm + NS_GM;
    float* bt_s = sm + NS_BT;
    float* mn_s = sm + NS_MEAN;
    float* rs_s = sm + NS_RSTD;

    const int t = threadIdx.x;

    for (int i = t; i < 40 * 96; i += 128) {
        int slot = i / 96, n = i - slot * 96;
        int kt = slot >> 2, q = slot & 3;
        int k2a = kt * 8 + q, k2b = k2a + 4;
        uint32_t la, lb;
        uint32_t ha = split_pair(Wu[(2 * k2a) * FIL + n], Wu[(2 * k2a + 1) * FIL + n], la);
        uint32_t hb = split_pair(Wu[(2 * k2b) * FIL + n], Wu[(2 * k2b + 1) * FIL + n], lb);
        B16[slot * 96 + (n ^ (2 * q))] = make_uint4(ha, hb, la, lb);
    }
    if (t < FIL) { bm_s[t] = bu[t]; gm_s[t] = gm[t]; bt_s[t] = bt[t]; }
    __syncthreads();

    const int lane = t & 31;
    const int w    = t >> 5;
    const int g    = lane >> 2;
    const int q    = lane & 3;
    const int r0 = w * 32 + g, r1 = r0 + 8, r2 = r0 + 16, r3 = r0 + 24;

    int gn[4] = {blockIdx.x * 128 + r0, blockIdx.x * 128 + r1,
                 blockIdx.x * 128 + r2, blockIdx.x * 128 + r3};
    const float* np[4];
    const float* ap[4];
    #pragma unroll
    for (int rr = 0; rr < 4; rr++) {
        int gc = gn[rr] < NT ? gn[rr] : NT - 1;
        np[rr] = nodes + (size_t)gc * Ff;
        ap[rr] = g_agg + (size_t)gc * FIL;
    }

    float c0[12][4], c1[12][4];
    #pragma unroll
    for (int nt = 0; nt < 12; nt++) {
        c0[nt][0]=0.f; c0[nt][1]=0.f; c0[nt][2]=0.f; c0[nt][3]=0.f;
        c1[nt][0]=0.f; c1[nt][1]=0.f; c1[nt][2]=0.f; c1[nt][3]=0.f;
    }
    const int gsw = g ^ (2 * q);

    #pragma unroll
    for (int kt = 0; kt < 10; kt++) {
        const float *pa, *pb, *pc, *pd;
        int off;
        if (kt < 4) { pa=np[0]; pb=np[1]; pc=np[2]; pd=np[3]; off = kt * 16; }
        else        { pa=ap[0]; pb=ap[1]; pc=ap[2]; pd=ap[3]; off = (kt - 4) * 16; }
        off += 2 * q;

        uint32_t ah0[4], al0[4], ah1[4], al1[4];
        load_split(pa, off, ah0[0], ah0[2], al0[0], al0[2]);
        load_split(pb, off, ah0[1], ah0[3], al0[1], al0[3]);
        load_split(pc, off, ah1[0], ah1[2], al1[0], al1[2]);
        load_split(pd, off, ah1[1], ah1[3], al1[1], al1[3]);

        const uint4* Bp = B16 + (kt * 4 + q) * 96 + gsw;
        #pragma unroll
        for (int nt = 0; nt < 12; nt++) {
            uint4 Bv = Bp[nt * 8];
            mma_bf16(c0[nt], ah0, Bv.x, Bv.y);
            mma_bf16(c0[nt], al0, Bv.x, Bv.y);
            mma_bf16(c0[nt], ah0, Bv.z, Bv.w);
            mma_bf16(c1[nt], ah1, Bv.x, Bv.y);
            mma_bf16(c1[nt], al1, Bv.x, Bv.y);
            mma_bf16(c1[nt], ah1, Bv.z, Bv.w);
        }
    }

    float sums[4] = {0.f, 0.f, 0.f, 0.f}, sqs[4] = {0.f, 0.f, 0.f, 0.f};
    #pragma unroll
    for (int nt = 0; nt < 12; nt++) {
        const int j = nt * 8 + 2 * q;
        const float bv0 = bm_s[j], bv1 = bm_s[j + 1];
        float v;
        v = fmaxf(c0[nt][0] + bv0, 0.f); c0[nt][0] = v; sums[0] += v; sqs[0] += v * v;
        v = fmaxf(c0[nt][1] + bv1, 0.f); c0[nt][1] = v; sums[0] += v; sqs[0] += v * v;
        v = fmaxf(c0[nt][2] + bv0, 0.f); c0[nt][2] = v; sums[1] += v; sqs[1] += v * v;
        v = fmaxf(c0[nt][3] + bv1, 0.f); c0[nt][3] = v; sums[1] += v; sqs[1] += v * v;
        v = fmaxf(c1[nt][0] + bv0, 0.f); c1[nt][0] = v; sums[2] += v; sqs[2] += v * v;
        v = fmaxf(c1[nt][1] + bv1, 0.f); c1[nt][1] = v; sums[2] += v; sqs[2] += v * v;
        v = fmaxf(c1[nt][2] + bv0, 0.f); c1[nt][2] = v; sums[3] += v; sqs[3] += v * v;
        v = fmaxf(c1[nt][3] + bv1, 0.f); c1[nt][3] = v; sums[3] += v; sqs[3] += v * v;
    }
    #pragma unroll
    for (int m = 1; m < 4; m <<= 1) {
        #pragma unroll
        for (int rr = 0; rr < 4; rr++) {
            sums[rr] += __shfl_xor_sync(0xffffffffu, sums[rr], m);
            sqs[rr]  += __shfl_xor_sync(0xffffffffu, sqs[rr],  m);
        }
    }
    if (q == 0) {
        const int rws[4] = {r0, r1, r2, r3};
        #pragma unroll
        for (int rr = 0; rr < 4; rr++) {
            float mean = sums[rr] * (1.f / FIL);
            float var  = sqs[rr] * (1.f / FIL) - mean * mean;
            mn_s[rws[rr]] = mean;
            rs_s[rws[rr]] = rsqrtf(var + LN_EPS);
        }
    }
    __syncthreads();

    #pragma unroll
    for (int nt = 0; nt < 12; nt++) {
        const int j = nt * 8 + 2 * q;
        *(float2*)(Ms + r0 * MSTR + j) = make_float2(c0[nt][0], c0[nt][1]);
        *(float2*)(Ms + r1 * MSTR + j) = make_float2(c0[nt][2], c0[nt][3]);
        *(float2*)(Ms + r2 * MSTR + j) = make_float2(c1[nt][0], c1[nt][1]);
        *(float2*)(Ms + r3 * MSTR + j) = make_float2(c1[nt][2], c1[nt][3]);
    }
    __syncthreads();

    for (int i = t; i < 128 * 24; i += 128) {
        const int row = i / 24;
        const int c4  = i - row * 24;
        const int j   = c4 * 4;
        const int ge  = blockIdx.x * 128 + row;
        if (ge >= NT) continue;
        const float mean = mn_s[row], rstd = rs_s[row];
        float4 v = *(const float4*)(Ms + row * MSTR + j);
        float4 o;
        o.x = (v.x - mean) * rstd * gm_s[j + 0] + bt_s[j + 0];
        o.y = (v.y - mean) * rstd * gm_s[j + 1] + bt_s[j + 1];
        o.z = (v.z - mean) * rstd * gm_s[j + 2] + bt_s[j + 2];
        o.w = (v.w - mean) * rstd * gm_s[j + 3] + bt_s[j + 3];
        ((float4*)(upd_out + (size_t)ge * FIL))[c4] = o;
    }
}

// ---------------- launch ----------------
extern "C" void kernel_launch(void* const* d_in, const int* in_sizes, int n_in,
                              void* d_out, int out_size) {
    const float* nodes = (const float*)d_in[0];
    const float* ef    = (const float*)d_in[1];
    const int*   edges = (const int*)  d_in[2];
    const float* Wm    = (const float*)d_in[3];
    const float* bm    = (const float*)d_in[4];
    const float* gm_m  = (const float*)d_in[5];
    const float* bt_m  = (const float*)d_in[6];
    const float* Wu    = (const float*)d_in[7];
    const float* bu    = (const float*)d_in[8];
    const float* gm_u  = (const float*)d_in[9];
    const float* bt_u  = (const float*)d_in[10];

    float* out = (float*)d_out;
    float* upd = out;                               // (B, N, FILTERS)
    float* msg = out + (size_t)Bq * Nn * FIL;       // (B, E, FILTERS)

    cudaFuncSetAttribute(pre_kernel, cudaFuncAttributeMaxDynamicSharedMemorySize,
                         P_SMEM_BYTES);
    cudaFuncSetAttribute(edge_kernel_mma, cudaFuncAttributeMaxDynamicSharedMemorySize,
                         E_SMEM_BYTES);
    cudaFuncSetAttribute(node_kernel_mma, cudaFuncAttributeMaxDynamicSharedMemorySize,
                         N_SMEM_BYTES);

    pre_kernel<<<(NT + 127) / 128, 256, P_SMEM_BYTES>>>(nodes, Wm);
    edge_kernel_mma<<<(Bq * Ee) / 128, 256, E_SMEM_BYTES>>>(
        ef, edges, Wm, bm, gm_m, bt_m, msg);
    node_kernel_mma<<<(NT + 127) / 128, 128, N_SMEM_BYTES>>>(
        nodes, Wu, bu, gm_u, bt_u, upd);
}

// round 12
// speedup vs baseline: 1.1833x; 1.0315x over previous
#include <cuda_runtime.h>
#include <cstdint>

#define Bq   8
#define Nn   5000
#define Ee   40000
#define Ff   64
#define FEe  16
#define FIL  96
#define DM   144
#define DU   160
#define LN_EPS 1e-3f
#define MSTR 104   // Ms row stride (words) — conflict-free
#define NT   (Bq * Nn)

__device__ __align__(16) float g_agg[(size_t)Bq * Nn * FIL];
__device__ __align__(16) float g_pre[(size_t)Bq * Nn * 192];   // [node][0:96]=src-term, [96:192]=dst-term

// packed bf16 hi/lo weight fragments (built once by pack_kernel)
__device__ __align__(16) uint4 g_Wpre[16 * 192];   // pre B: combined [Wm(0:64)|Wm(64:128)]
__device__ __align__(16) uint4 g_Wef[4 * 96];      // edge B: Wm[128:144]
__device__ __align__(16) uint4 g_Wun[40 * 96];     // node B: Wu

// ---------------- helpers ----------------
__device__ __forceinline__ void red4(float* addr, float4 v) {
    asm volatile("red.global.add.v4.f32 [%0], {%1,%2,%3,%4};"
                 :: "l"(addr), "f"(v.x), "f"(v.y), "f"(v.z), "f"(v.w) : "memory");
}
// split (x,y) fp32 pair into bf16x2 hi + bf16x2 lo (lo = residual)
__device__ __forceinline__ uint32_t split_pair(float x, float y, uint32_t& lo2) {
    uint32_t h;
    asm("cvt.rn.bf16x2.f32 %0, %1, %2;" : "=r"(h) : "f"(y), "f"(x));
    float hx = __uint_as_float(h << 16);
    float hy = __uint_as_float(h & 0xffff0000u);
    float rx = x - hx, ry = y - hy;
    asm("cvt.rn.bf16x2.f32 %0, %1, %2;" : "=r"(lo2) : "f"(ry), "f"(rx));
    return h;
}
__device__ __forceinline__ void mma_bf16(float* c, const uint32_t* a,
                                         uint32_t b0, uint32_t b1) {
    asm volatile(
        "mma.sync.aligned.m16n8k16.row.col.f32.bf16.bf16.f32 "
        "{%0,%1,%2,%3}, {%4,%5,%6,%7}, {%8,%9}, {%0,%1,%2,%3};"
        : "+f"(c[0]), "+f"(c[1]), "+f"(c[2]), "+f"(c[3])
        : "r"(a[0]), "r"(a[1]), "r"(a[2]), "r"(a[3]), "r"(b0), "r"(b1));
}
__device__ __forceinline__ void load_split(const float* p, int off,
                                           uint32_t& h0, uint32_t& h2,
                                           uint32_t& l0, uint32_t& l2) {
    float2 x0 = *(const float2*)(p + off);
    float2 x2 = *(const float2*)(p + off + 8);
    h0 = split_pair(x0.x, x0.y, l0);
    h2 = split_pair(x2.x, x2.y, l2);
}

// ================= pack kernel =================
// Builds all packed weight arrays once + zeroes g_agg.
__global__ void __launch_bounds__(256) pack_kernel(
    const float* __restrict__ Wm, const float* __restrict__ Wu)
{
    const int t = threadIdx.x;
    const size_t gtid = (size_t)blockIdx.x * 256 + t;
    const size_t gstr = (size_t)gridDim.x * 256;

    // zero g_agg
    {
        float4* p = (float4*)g_agg;
        for (size_t i = gtid; i < (size_t)NT * FIL / 4; i += gstr)
            p[i] = make_float4(0.f, 0.f, 0.f, 0.f);
    }
    // pre weights: combined (64 x 192)
    for (size_t i = gtid; i < 16 * 192; i += gstr) {
        int slot = (int)i / 192, n = (int)i - slot * 192;
        int kt = slot >> 2, qs = slot & 3;
        int ka = (kt * 8 + qs) * 2;
        int kb = ka + 8;
        const int col = (n < 96) ? n : (n - 96);
        const int ro  = (n < 96) ? 0 : 64;
        uint32_t la, lb;
        uint32_t ha = split_pair(Wm[(ro + ka) * FIL + col], Wm[(ro + ka + 1) * FIL + col], la);
        uint32_t hb = split_pair(Wm[(ro + kb) * FIL + col], Wm[(ro + kb + 1) * FIL + col], lb);
        g_Wpre[slot * 192 + (n ^ (2 * qs))] = make_uint4(ha, hb, la, lb);
    }
    // edge weights: Wm[128:144]
    for (size_t i = gtid; i < 4 * 96; i += gstr) {
        int qs = (int)i / 96, n = (int)i - qs * 96;
        uint32_t la, lb;
        uint32_t ha = split_pair(Wm[(128 + 2 * qs) * FIL + n], Wm[(129 + 2 * qs) * FIL + n], la);
        uint32_t hb = split_pair(Wm[(136 + 2 * qs) * FIL + n], Wm[(137 + 2 * qs) * FIL + n], lb);
        g_Wef[qs * 96 + (n ^ (2 * qs))] = make_uint4(ha, hb, la, lb);
    }
    // node weights: Wu (160 x 96)
    for (size_t i = gtid; i < 40 * 96; i += gstr) {
        int slot = (int)i / 96, n = (int)i - slot * 96;
        int kt = slot >> 2, q = slot & 3;
        int k2a = kt * 8 + q, k2b = k2a + 4;
        uint32_t la, lb;
        uint32_t ha = split_pair(Wu[(2 * k2a) * FIL + n], Wu[(2 * k2a + 1) * FIL + n], la);
        uint32_t hb = split_pair(Wu[(2 * k2b) * FIL + n], Wu[(2 * k2b + 1) * FIL + n], lb);
        g_Wun[slot * 96 + (n ^ (2 * q))] = make_uint4(ha, hb, la, lb);
    }
}

// ================= pre kernel =================
// g_pre[row][0:192] = nodes[row] @ [Wm(0:64) | Wm(64:128)]. No smem; B via L1.
__global__ void __launch_bounds__(256, 2) pre_kernel(
    const float* __restrict__ nodes)
{
    const int t = threadIdx.x;
    const int lane = t & 31;
    const int w    = t >> 5;
    const int g    = lane >> 2;
    const int q    = lane & 3;
    const int r0 = w * 16 + g;
    const int gn0 = blockIdx.x * 128 + r0;
    const int gn1 = gn0 + 8;
    const int g0c = gn0 < NT ? gn0 : NT - 1;
    const int g1c = gn1 < NT ? gn1 : NT - 1;
    const float* n0 = nodes + (size_t)g0c * Ff;
    const float* n1 = nodes + (size_t)g1c * Ff;

    float c[24][4];
    #pragma unroll
    for (int nt = 0; nt < 24; nt++) { c[nt][0]=0.f; c[nt][1]=0.f; c[nt][2]=0.f; c[nt][3]=0.f; }

    const int gsw = g ^ (2 * q);
    const int qo  = 2 * q;

    #pragma unroll
    for (int kt = 0; kt < 4; kt++) {
        uint32_t ah[4], al[4];
        load_split(n0, kt * 16 + qo, ah[0], ah[2], al[0], al[2]);
        load_split(n1, kt * 16 + qo, ah[1], ah[3], al[1], al[3]);
        const uint4* Bp = g_Wpre + (kt * 4 + q) * 192 + gsw;
        #pragma unroll
        for (int nt = 0; nt < 24; nt++) {
            uint4 Bv = Bp[nt * 8];
            mma_bf16(c[nt], ah, Bv.x, Bv.y);
            mma_bf16(c[nt], al, Bv.x, Bv.y);
            mma_bf16(c[nt], ah, Bv.z, Bv.w);
        }
    }

    if (gn0 < NT) {
        float* o = g_pre + (size_t)gn0 * 192 + qo;
        #pragma unroll
        for (int nt = 0; nt < 24; nt++)
            *(float2*)(o + nt * 8) = make_float2(c[nt][0], c[nt][1]);
    }
    if (gn1 < NT) {
        float* o = g_pre + (size_t)gn1 * 192 + qo;
        #pragma unroll
        for (int nt = 0; nt < 24; nt++)
            *(float2*)(o + nt * 8) = make_float2(c[nt][2], c[nt][3]);
    }
}

// ================= edge kernel =================
// 128 edges/block. c init = g_pre[src] + g_pre[dst] + bias, then ef GEMM (1 k-step,
// B via L1), relu + LN, staged store + red4.
#define XS_MS    0             // 128 x 104 = 13312 words
#define XS_BM    13312
#define XS_GM    13408
#define XS_BT    13504
#define XS_SEB   13600         // 128 int2 = 256 words
#define XS_TOTAL 13856
#define E_SMEM_BYTES (XS_TOTAL * 4)

__global__ void __launch_bounds__(256, 3) edge_kernel_mma(
    const float* __restrict__ ef,    const int*   __restrict__ edges,
    const float* __restrict__ bm,    const float* __restrict__ gm,
    const float* __restrict__ bt,    float* __restrict__ msg_out)
{
    extern __shared__ float sm[];
    float* Ms   = sm + XS_MS;         // stride MSTR
    float* bm_s = sm + XS_BM;
    float* gm_s = sm + XS_GM;
    float* bt_s = sm + XS_BT;
    int2*  seb  = (int2*)(sm + XS_SEB);

    const int t = threadIdx.x;

    if (t < FIL) { bm_s[t] = bm[t]; gm_s[t] = gm[t]; bt_s[t] = bt[t]; }
    if (t < 128) seb[t] = ((const int2*)edges)[blockIdx.x * 128 + t];
    __syncthreads();

    const int lane = t & 31;
    const int w    = t >> 5;
    const int g    = lane >> 2;
    const int q    = lane & 3;
    const int r0 = w * 16 + g, r1 = r0 + 8;
    const int ge0 = blockIdx.x * 128 + r0;
    const int ge1 = ge0 + 8;
    const int b0 = ge0 / Ee, b1 = ge1 / Ee;
    const int2 e0 = seb[r0], e1 = seb[r1];
    const int gsw = g ^ (2 * q);
    const int qo  = 2 * q;

    // ---- init accumulators with gathered g_pre terms + bias (loads lead) ----
    const float* pA = g_pre + (size_t)(b0 * Nn + e0.x) * 192;        // src0 term
    const float* pB = g_pre + (size_t)(b0 * Nn + e0.y) * 192 + 96;   // dst0 term
    const float* pC = g_pre + (size_t)(b1 * Nn + e1.x) * 192;
    const float* pD = g_pre + (size_t)(b1 * Nn + e1.y) * 192 + 96;

    float c[12][4];
    #pragma unroll
    for (int nt = 0; nt < 12; nt++) {
        const int j = nt * 8 + qo;
        float2 xa = *(const float2*)(pA + j);
        float2 xb = *(const float2*)(pB + j);
        float2 xc = *(const float2*)(pC + j);
        float2 xd = *(const float2*)(pD + j);
        const float bv0 = bm_s[j], bv1 = bm_s[j + 1];
        c[nt][0] = xa.x + xb.x + bv0;
        c[nt][1] = xa.y + xb.y + bv1;
        c[nt][2] = xc.x + xd.x + bv0;
        c[nt][3] = xc.y + xd.y + bv1;
    }

    // ---- ef GEMM accumulates on top: single k-step, 3 terms (B via L1) ----
    {
        uint32_t ah[4], al[4];
        load_split(ef + (size_t)ge0 * FEe, qo, ah[0], ah[2], al[0], al[2]);
        load_split(ef + (size_t)ge1 * FEe, qo, ah[1], ah[3], al[1], al[3]);
        const uint4* Bp = g_Wef + q * 96 + gsw;
        #pragma unroll
        for (int nt = 0; nt < 12; nt++) {
            uint4 Bv = Bp[nt * 8];
            mma_bf16(c[nt], ah, Bv.x, Bv.y);
            mma_bf16(c[nt], al, Bv.x, Bv.y);
            mma_bf16(c[nt], ah, Bv.z, Bv.w);
        }
    }

    // ---- relu + LN stats ----
    float sum0 = 0.f, sq0 = 0.f, sum1 = 0.f, sq1 = 0.f;
    #pragma unroll
    for (int nt = 0; nt < 12; nt++) {
        float v0 = fmaxf(c[nt][0], 0.f);
        float v1 = fmaxf(c[nt][1], 0.f);
        float v2 = fmaxf(c[nt][2], 0.f);
        float v3 = fmaxf(c[nt][3], 0.f);
        c[nt][0] = v0; c[nt][1] = v1; c[nt][2] = v2; c[nt][3] = v3;
        sum0 += v0 + v1;  sq0 += v0 * v0 + v1 * v1;
        sum1 += v2 + v3;  sq1 += v2 * v2 + v3 * v3;
    }
    #pragma unroll
    for (int m = 1; m < 4; m <<= 1) {
        sum0 += __shfl_xor_sync(0xffffffffu, sum0, m);
        sq0  += __shfl_xor_sync(0xffffffffu, sq0,  m);
        sum1 += __shfl_xor_sync(0xffffffffu, sum1, m);
        sq1  += __shfl_xor_sync(0xffffffffu, sq1,  m);
    }
    const float mean0 = sum0 * (1.f / FIL);
    const float rstd0 = rsqrtf(sq0 * (1.f / FIL) - mean0 * mean0 + LN_EPS);
    const float mean1 = sum1 * (1.f / FIL);
    const float rstd1 = rsqrtf(sq1 * (1.f / FIL) - mean1 * mean1 + LN_EPS);

    // ---- apply LN, stage final messages ----
    #pragma unroll
    for (int nt = 0; nt < 12; nt++) {
        const int j = nt * 8 + qo;
        const float g0 = gm_s[j], g1 = gm_s[j + 1];
        const float t0 = bt_s[j], t1 = bt_s[j + 1];
        *(float2*)(Ms + r0 * MSTR + j) = make_float2(
            (c[nt][0] - mean0) * rstd0 * g0 + t0,
            (c[nt][1] - mean0) * rstd0 * g1 + t1);
        *(float2*)(Ms + r1 * MSTR + j) = make_float2(
            (c[nt][2] - mean1) * rstd1 * g0 + t0,
            (c[nt][3] - mean1) * rstd1 * g1 + t1);
    }
    __syncthreads();

    // ---- coalesced store + vector atomics ----
    for (int i = t; i < 128 * 24; i += 256) {
        const int row = i / 24;
        const int c4  = i - row * 24;
        const int j   = c4 * 4;
        float4 o = *(const float4*)(Ms + row * MSTR + j);
        const int ge = blockIdx.x * 128 + row;
        const int b  = ge / Ee;
        ((float4*)(msg_out + (size_t)ge * FIL))[c4] = o;
        red4(g_agg + ((size_t)b * Nn + seb[row].y) * FIL + j, o);
    }
}

// ================= node kernel (B via L1, no staging) =================
#define NS_BM    13312
#define NS_GM    13408
#define NS_BT    13504
#define NS_MEAN  13600
#define NS_RSTD  13728
#define NS_TOTAL 13856
#define N_SMEM_BYTES (NS_TOTAL * 4)

__global__ void __launch_bounds__(128) node_kernel_mma(
    const float* __restrict__ nodes, const float* __restrict__ bu,
    const float* __restrict__ gm,    const float* __restrict__ bt,
    float* __restrict__ upd_out)
{
    extern __shared__ float sm[];
    float* Ms   = sm;
    float* bm_s = sm + NS_BM;
    float* gm_s = sm + NS_GM;
    float* bt_s = sm + NS_BT;
    float* mn_s = sm + NS_MEAN;
    float* rs_s = sm + NS_RSTD;

    const int t = threadIdx.x;

    if (t < FIL) { bm_s[t] = bu[t]; gm_s[t] = gm[t]; bt_s[t] = bt[t]; }
    __syncthreads();

    const int lane = t & 31;
    const int w    = t >> 5;
    const int g    = lane >> 2;
    const int q    = lane & 3;
    const int r0 = w * 32 + g, r1 = r0 + 8, r2 = r0 + 16, r3 = r0 + 24;

    int gn[4] = {blockIdx.x * 128 + r0, blockIdx.x * 128 + r1,
                 blockIdx.x * 128 + r2, blockIdx.x * 128 + r3};
    const float* np[4];
    const float* ap[4];
    #pragma unroll
    for (int rr = 0; rr < 4; rr++) {
        int gc = gn[rr] < NT ? gn[rr] : NT - 1;
        np[rr] = nodes + (size_t)gc * Ff;
        ap[rr] = g_agg + (size_t)gc * FIL;
    }

    float c0[12][4], c1[12][4];
    #pragma unroll
    for (int nt = 0; nt < 12; nt++) {
        c0[nt][0]=0.f; c0[nt][1]=0.f; c0[nt][2]=0.f; c0[nt][3]=0.f;
        c1[nt][0]=0.f; c1[nt][1]=0.f; c1[nt][2]=0.f; c1[nt][3]=0.f;
    }
    const int gsw = g ^ (2 * q);

    #pragma unroll
    for (int kt = 0; kt < 10; kt++) {
        const float *pa, *pb, *pc, *pd;
        int off;
        if (kt < 4) { pa=np[0]; pb=np[1]; pc=np[2]; pd=np[3]; off = kt * 16; }
        else        { pa=ap[0]; pb=ap[1]; pc=ap[2]; pd=ap[3]; off = (kt - 4) * 16; }
        off += 2 * q;

        uint32_t ah0[4], al0[4], ah1[4], al1[4];
        load_split(pa, off, ah0[0], ah0[2], al0[0], al0[2]);
        load_split(pb, off, ah0[1], ah0[3], al0[1], al0[3]);
        load_split(pc, off, ah1[0], ah1[2], al1[0], al1[2]);
        load_split(pd, off, ah1[1], ah1[3], al1[1], al1[3]);

        const uint4* Bp = g_Wun + (kt * 4 + q) * 96 + gsw;
        #pragma unroll
        for (int nt = 0; nt < 12; nt++) {
            uint4 Bv = Bp[nt * 8];
            mma_bf16(c0[nt], ah0, Bv.x, Bv.y);
            mma_bf16(c0[nt], al0, Bv.x, Bv.y);
            mma_bf16(c0[nt], ah0, Bv.z, Bv.w);
            mma_bf16(c1[nt], ah1, Bv.x, Bv.y);
            mma_bf16(c1[nt], al1, Bv.x, Bv.y);
            mma_bf16(c1[nt], ah1, Bv.z, Bv.w);
        }
    }

    float sums[4] = {0.f, 0.f, 0.f, 0.f}, sqs[4] = {0.f, 0.f, 0.f, 0.f};
    #pragma unroll
    for (int nt = 0; nt < 12; nt++) {
        const int j = nt * 8 + 2 * q;
        const float bv0 = bm_s[j], bv1 = bm_s[j + 1];
        float v;
        v = fmaxf(c0[nt][0] + bv0, 0.f); c0[nt][0] = v; sums[0] += v; sqs[0] += v * v;
        v = fmaxf(c0[nt][1] + bv1, 0.f); c0[nt][1] = v; sums[0] += v; sqs[0] += v * v;
        v = fmaxf(c0[nt][2] + bv0, 0.f); c0[nt][2] = v; sums[1] += v; sqs[1] += v * v;
        v = fmaxf(c0[nt][3] + bv1, 0.f); c0[nt][3] = v; sums[1] += v; sqs[1] += v * v;
        v = fmaxf(c1[nt][0] + bv0, 0.f); c1[nt][0] = v; sums[2] += v; sqs[2] += v * v;
        v = fmaxf(c1[nt][1] + bv1, 0.f); c1[nt][1] = v; sums[2] += v; sqs[2] += v * v;
        v = fmaxf(c1[nt][2] + bv0, 0.f); c1[nt][2] = v; sums[3] += v; sqs[3] += v * v;
        v = fmaxf(c1[nt][3] + bv1, 0.f); c1[nt][3] = v; sums[3] += v; sqs[3] += v * v;
    }
    #pragma unroll
    for (int m = 1; m < 4; m <<= 1) {
        #pragma unroll
        for (int rr = 0; rr < 4; rr++) {
            sums[rr] += __shfl_xor_sync(0xffffffffu, sums[rr], m);
            sqs[rr]  += __shfl_xor_sync(0xffffffffu, sqs[rr],  m);
        }
    }
    if (q == 0) {
        const int rws[4] = {r0, r1, r2, r3};
        #pragma unroll
        for (int rr = 0; rr < 4; rr++) {
            float mean = sums[rr] * (1.f / FIL);
            float var  = sqs[rr] * (1.f / FIL) - mean * mean;
            mn_s[rws[rr]] = mean;
            rs_s[rws[rr]] = rsqrtf(var + LN_EPS);
        }
    }
    __syncthreads();

    #pragma unroll
    for (int nt = 0; nt < 12; nt++) {
        const int j = nt * 8 + 2 * q;
        *(float2*)(Ms + r0 * MSTR + j) = make_float2(c0[nt][0], c0[nt][1]);
        *(float2*)(Ms + r1 * MSTR + j) = make_float2(c0[nt][2], c0[nt][3]);
        *(float2*)(Ms + r2 * MSTR + j) = make_float2(c1[nt][0], c1[nt][1]);
        *(float2*)(Ms + r3 * MSTR + j) = make_float2(c1[nt][2], c1[nt][3]);
    }
    __syncthreads();

    for (int i = t; i < 128 * 24; i += 128) {
        const int row = i / 24;
        const int c4  = i - row * 24;
        const int j   = c4 * 4;
        const int ge  = blockIdx.x * 128 + row;
        if (ge >= NT) continue;
        const float mean = mn_s[row], rstd = rs_s[row];
        float4 v = *(const float4*)(Ms + row * MSTR + j);
        float4 o;
        o.x = (v.x - mean) * rstd * gm_s[j + 0] + bt_s[j + 0];
        o.y = (v.y - mean) * rstd * gm_s[j + 1] + bt_s[j + 1];
        o.z = (v.z - mean) * rstd * gm_s[j + 2] + bt_s[j + 2];
        o.w = (v.w - mean) * rstd * gm_s[j + 3] + bt_s[j + 3];
        ((float4*)(upd_out + (size_t)ge * FIL))[c4] = o;
    }
}

// ---------------- launch ----------------
extern "C" void kernel_launch(void* const* d_in, const int* in_sizes, int n_in,
                              void* d_out, int out_size) {
    const float* nodes = (const float*)d_in[0];
    const float* ef    = (const float*)d_in[1];
    const int*   edges = (const int*)  d_in[2];
    const float* Wm    = (const float*)d_in[3];
    const float* bm    = (const float*)d_in[4];
    const float* gm_m  = (const float*)d_in[5];
    const float* bt_m  = (const float*)d_in[6];
    const float* Wu    = (const float*)d_in[7];
    const float* bu    = (const float*)d_in[8];
    const float* gm_u  = (const float*)d_in[9];
    const float* bt_u  = (const float*)d_in[10];

    float* out = (float*)d_out;
    float* upd = out;                               // (B, N, FILTERS)
    float* msg = out + (size_t)Bq * Nn * FIL;       // (B, E, FILTERS)

    cudaFuncSetAttribute(edge_kernel_mma, cudaFuncAttributeMaxDynamicSharedMemorySize,
                         E_SMEM_BYTES);
    cudaFuncSetAttribute(node_kernel_mma, cudaFuncAttributeMaxDynamicSharedMemorySize,
                         N_SMEM_BYTES);

    pack_kernel<<<232, 256>>>(Wm, Wu);
    pre_kernel<<<(NT + 127) / 128, 256>>>(nodes);
    edge_kernel_mma<<<(Bq * Ee) / 128, 256, E_SMEM_BYTES>>>(
        ef, edges, bm, gm_m, bt_m, msg);
    node_kernel_mma<<<(NT + 127) / 128, 128, N_SMEM_BYTES>>>(
        nodes, bu, gm_u, bt_u, upd);
}

// round 13
// speedup vs baseline: 1.2151x; 1.0268x over previous
#include <cuda_runtime.h>
#include <cstdint>

#define Bq   8
#define Nn   5000
#define Ee   40000
#define Ff   64
#define FEe  16
#define FIL  96
#define DM   144
#define DU   160
#define LN_EPS 1e-3f
#define MSTR 104   // Ms row stride (words) — conflict-free
#define NT   (Bq * Nn)

__device__ __align__(16) float g_agg[(size_t)Bq * Nn * FIL];
__device__ __align__(16) float g_pre[(size_t)Bq * Nn * 192];   // [node][0:96]=src-term, [96:192]=dst-term

// packed bf16 hi/lo weight fragments (built once by pack_kernel)
__device__ __align__(16) uint4 g_Wpre[16 * 192];   // pre B: combined [Wm(0:64)|Wm(64:128)]
__device__ __align__(16) uint4 g_Wef[4 * 96];      // edge B: Wm[128:144]
__device__ __align__(16) uint4 g_Wun[40 * 96];     // node B: Wu

// ---------------- helpers ----------------
__device__ __forceinline__ void red4(float* addr, float4 v) {
    asm volatile("red.global.add.v4.f32 [%0], {%1,%2,%3,%4};"
                 :: "l"(addr), "f"(v.x), "f"(v.y), "f"(v.z), "f"(v.w) : "memory");
}
// split (x,y) fp32 pair into bf16x2 hi + bf16x2 lo (lo = residual)
__device__ __forceinline__ uint32_t split_pair(float x, float y, uint32_t& lo2) {
    uint32_t h;
    asm("cvt.rn.bf16x2.f32 %0, %1, %2;" : "=r"(h) : "f"(y), "f"(x));
    float hx = __uint_as_float(h << 16);
    float hy = __uint_as_float(h & 0xffff0000u);
    float rx = x - hx, ry = y - hy;
    asm("cvt.rn.bf16x2.f32 %0, %1, %2;" : "=r"(lo2) : "f"(ry), "f"(rx));
    return h;
}
__device__ __forceinline__ void mma_bf16(float* c, const uint32_t* a,
                                         uint32_t b0, uint32_t b1) {
    asm volatile(
        "mma.sync.aligned.m16n8k16.row.col.f32.bf16.bf16.f32 "
        "{%0,%1,%2,%3}, {%4,%5,%6,%7}, {%8,%9}, {%0,%1,%2,%3};"
        : "+f"(c[0]), "+f"(c[1]), "+f"(c[2]), "+f"(c[3])
        : "r"(a[0]), "r"(a[1]), "r"(a[2]), "r"(a[3]), "r"(b0), "r"(b1));
}
__device__ __forceinline__ void load_split(const float* p, int off,
                                           uint32_t& h0, uint32_t& h2,
                                           uint32_t& l0, uint32_t& l2) {
    float2 x0 = *(const float2*)(p + off);
    float2 x2 = *(const float2*)(p + off + 8);
    h0 = split_pair(x0.x, x0.y, l0);
    h2 = split_pair(x2.x, x2.y, l2);
}

// ================= pack kernel =================
__global__ void __launch_bounds__(256) pack_kernel(
    const float* __restrict__ Wm, const float* __restrict__ Wu)
{
    const int t = threadIdx.x;
    const size_t gtid = (size_t)blockIdx.x * 256 + t;
    const size_t gstr = (size_t)gridDim.x * 256;

    // zero g_agg
    {
        float4* p = (float4*)g_agg;
        for (size_t i = gtid; i < (size_t)NT * FIL / 4; i += gstr)
            p[i] = make_float4(0.f, 0.f, 0.f, 0.f);
    }
    // pre weights: combined (64 x 192)
    for (size_t i = gtid; i < 16 * 192; i += gstr) {
        int slot = (int)i / 192, n = (int)i - slot * 192;
        int kt = slot >> 2, qs = slot & 3;
        int ka = (kt * 8 + qs) * 2;
        int kb = ka + 8;
        const int col = (n < 96) ? n : (n - 96);
        const int ro  = (n < 96) ? 0 : 64;
        uint32_t la, lb;
        uint32_t ha = split_pair(Wm[(ro + ka) * FIL + col], Wm[(ro + ka + 1) * FIL + col], la);
        uint32_t hb = split_pair(Wm[(ro + kb) * FIL + col], Wm[(ro + kb + 1) * FIL + col], lb);
        g_Wpre[slot * 192 + (n ^ (2 * qs))] = make_uint4(ha, hb, la, lb);
    }
    // edge weights: Wm[128:144]
    for (size_t i = gtid; i < 4 * 96; i += gstr) {
        int qs = (int)i / 96, n = (int)i - qs * 96;
        uint32_t la, lb;
        uint32_t ha = split_pair(Wm[(128 + 2 * qs) * FIL + n], Wm[(129 + 2 * qs) * FIL + n], la);
        uint32_t hb = split_pair(Wm[(136 + 2 * qs) * FIL + n], Wm[(137 + 2 * qs) * FIL + n], lb);
        g_Wef[qs * 96 + (n ^ (2 * qs))] = make_uint4(ha, hb, la, lb);
    }
    // node weights: Wu (160 x 96)
    for (size_t i = gtid; i < 40 * 96; i += gstr) {
        int slot = (int)i / 96, n = (int)i - slot * 96;
        int kt = slot >> 2, q = slot & 3;
        int k2a = kt * 8 + q, k2b = k2a + 4;
        uint32_t la, lb;
        uint32_t ha = split_pair(Wu[(2 * k2a) * FIL + n], Wu[(2 * k2a + 1) * FIL + n], la);
        uint32_t hb = split_pair(Wu[(2 * k2b) * FIL + n], Wu[(2 * k2b + 1) * FIL + n], lb);
        g_Wun[slot * 96 + (n ^ (2 * q))] = make_uint4(ha, hb, la, lb);
    }
}

// ================= pre kernel (unchanged) =================
__global__ void __launch_bounds__(256, 2) pre_kernel(
    const float* __restrict__ nodes)
{
    const int t = threadIdx.x;
    const int lane = t & 31;
    const int w    = t >> 5;
    const int g    = lane >> 2;
    const int q    = lane & 3;
    const int r0 = w * 16 + g;
    const int gn0 = blockIdx.x * 128 + r0;
    const int gn1 = gn0 + 8;
    const int g0c = gn0 < NT ? gn0 : NT - 1;
    const int g1c = gn1 < NT ? gn1 : NT - 1;
    const float* n0 = nodes + (size_t)g0c * Ff;
    const float* n1 = nodes + (size_t)g1c * Ff;

    float c[24][4];
    #pragma unroll
    for (int nt = 0; nt < 24; nt++) { c[nt][0]=0.f; c[nt][1]=0.f; c[nt][2]=0.f; c[nt][3]=0.f; }

    const int gsw = g ^ (2 * q);
    const int qo  = 2 * q;

    #pragma unroll
    for (int kt = 0; kt < 4; kt++) {
        uint32_t ah[4], al[4];
        load_split(n0, kt * 16 + qo, ah[0], ah[2], al[0], al[2]);
        load_split(n1, kt * 16 + qo, ah[1], ah[3], al[1], al[3]);
        const uint4* Bp = g_Wpre + (kt * 4 + q) * 192 + gsw;
        #pragma unroll
        for (int nt = 0; nt < 24; nt++) {
            uint4 Bv = Bp[nt * 8];
            mma_bf16(c[nt], ah, Bv.x, Bv.y);
            mma_bf16(c[nt], al, Bv.x, Bv.y);
            mma_bf16(c[nt], ah, Bv.z, Bv.w);
        }
    }

    if (gn0 < NT) {
        float* o = g_pre + (size_t)gn0 * 192 + qo;
        #pragma unroll
        for (int nt = 0; nt < 24; nt++)
            *(float2*)(o + nt * 8) = make_float2(c[nt][0], c[nt][1]);
    }
    if (gn1 < NT) {
        float* o = g_pre + (size_t)gn1 * 192 + qo;
        #pragma unroll
        for (int nt = 0; nt < 24; nt++)
            *(float2*)(o + nt * 8) = make_float2(c[nt][2], c[nt][3]);
    }
}

// ================= edge kernel (unchanged from R12) =================
#define XS_MS    0             // 128 x 104 = 13312 words
#define XS_BM    13312
#define XS_GM    13408
#define XS_BT    13504
#define XS_SEB   13600         // 128 int2 = 256 words
#define XS_TOTAL 13856
#define E_SMEM_BYTES (XS_TOTAL * 4)

__global__ void __launch_bounds__(256, 3) edge_kernel_mma(
    const float* __restrict__ ef,    const int*   __restrict__ edges,
    const float* __restrict__ bm,    const float* __restrict__ gm,
    const float* __restrict__ bt,    float* __restrict__ msg_out)
{
    extern __shared__ float sm[];
    float* Ms   = sm + XS_MS;         // stride MSTR
    float* bm_s = sm + XS_BM;
    float* gm_s = sm + XS_GM;
    float* bt_s = sm + XS_BT;
    int2*  seb  = (int2*)(sm + XS_SEB);

    const int t = threadIdx.x;

    if (t < FIL) { bm_s[t] = bm[t]; gm_s[t] = gm[t]; bt_s[t] = bt[t]; }
    if (t < 128) seb[t] = ((const int2*)edges)[blockIdx.x * 128 + t];
    __syncthreads();

    const int lane = t & 31;
    const int w    = t >> 5;
    const int g    = lane >> 2;
    const int q    = lane & 3;
    const int r0 = w * 16 + g, r1 = r0 + 8;
    const int ge0 = blockIdx.x * 128 + r0;
    const int ge1 = ge0 + 8;
    const int b0 = ge0 / Ee, b1 = ge1 / Ee;
    const int2 e0 = seb[r0], e1 = seb[r1];
    const int gsw = g ^ (2 * q);
    const int qo  = 2 * q;

    const float* pA = g_pre + (size_t)(b0 * Nn + e0.x) * 192;
    const float* pB = g_pre + (size_t)(b0 * Nn + e0.y) * 192 + 96;
    const float* pC = g_pre + (size_t)(b1 * Nn + e1.x) * 192;
    const float* pD = g_pre + (size_t)(b1 * Nn + e1.y) * 192 + 96;

    float c[12][4];
    #pragma unroll
    for (int nt = 0; nt < 12; nt++) {
        const int j = nt * 8 + qo;
        float2 xa = *(const float2*)(pA + j);
        float2 xb = *(const float2*)(pB + j);
        float2 xc = *(const float2*)(pC + j);
        float2 xd = *(const float2*)(pD + j);
        const float bv0 = bm_s[j], bv1 = bm_s[j + 1];
        c[nt][0] = xa.x + xb.x + bv0;
        c[nt][1] = xa.y + xb.y + bv1;
        c[nt][2] = xc.x + xd.x + bv0;
        c[nt][3] = xc.y + xd.y + bv1;
    }

    {
        uint32_t ah[4], al[4];
        load_split(ef + (size_t)ge0 * FEe, qo, ah[0], ah[2], al[0], al[2]);
        load_split(ef + (size_t)ge1 * FEe, qo, ah[1], ah[3], al[1], al[3]);
        const uint4* Bp = g_Wef + q * 96 + gsw;
        #pragma unroll
        for (int nt = 0; nt < 12; nt++) {
            uint4 Bv = Bp[nt * 8];
            mma_bf16(c[nt], ah, Bv.x, Bv.y);
            mma_bf16(c[nt], al, Bv.x, Bv.y);
            mma_bf16(c[nt], ah, Bv.z, Bv.w);
        }
    }

    float sum0 = 0.f, sq0 = 0.f, sum1 = 0.f, sq1 = 0.f;
    #pragma unroll
    for (int nt = 0; nt < 12; nt++) {
        float v0 = fmaxf(c[nt][0], 0.f);
        float v1 = fmaxf(c[nt][1], 0.f);
        float v2 = fmaxf(c[nt][2], 0.f);
        float v3 = fmaxf(c[nt][3], 0.f);
        c[nt][0] = v0; c[nt][1] = v1; c[nt][2] = v2; c[nt][3] = v3;
        sum0 += v0 + v1;  sq0 += v0 * v0 + v1 * v1;
        sum1 += v2 + v3;  sq1 += v2 * v2 + v3 * v3;
    }
    #pragma unroll
    for (int m = 1; m < 4; m <<= 1) {
        sum0 += __shfl_xor_sync(0xffffffffu, sum0, m);
        sq0  += __shfl_xor_sync(0xffffffffu, sq0,  m);
        sum1 += __shfl_xor_sync(0xffffffffu, sum1, m);
        sq1  += __shfl_xor_sync(0xffffffffu, sq1,  m);
    }
    const float mean0 = sum0 * (1.f / FIL);
    const float rstd0 = rsqrtf(sq0 * (1.f / FIL) - mean0 * mean0 + LN_EPS);
    const float mean1 = sum1 * (1.f / FIL);
    const float rstd1 = rsqrtf(sq1 * (1.f / FIL) - mean1 * mean1 + LN_EPS);

    #pragma unroll
    for (int nt = 0; nt < 12; nt++) {
        const int j = nt * 8 + qo;
        const float g0 = gm_s[j], g1 = gm_s[j + 1];
        const float t0 = bt_s[j], t1 = bt_s[j + 1];
        *(float2*)(Ms + r0 * MSTR + j) = make_float2(
            (c[nt][0] - mean0) * rstd0 * g0 + t0,
            (c[nt][1] - mean0) * rstd0 * g1 + t1);
        *(float2*)(Ms + r1 * MSTR + j) = make_float2(
            (c[nt][2] - mean1) * rstd1 * g0 + t0,
            (c[nt][3] - mean1) * rstd1 * g1 + t1);
    }
    __syncthreads();

    for (int i = t; i < 128 * 24; i += 256) {
        const int row = i / 24;
        const int c4  = i - row * 24;
        const int j   = c4 * 4;
        float4 o = *(const float4*)(Ms + row * MSTR + j);
        const int ge = blockIdx.x * 128 + row;
        const int b  = ge / Ee;
        ((float4*)(msg_out + (size_t)ge * FIL))[c4] = o;
        red4(g_agg + ((size_t)b * Nn + seb[row].y) * FIL + j, o);
    }
}

// ================= node kernel: 8 warps x 16 rows (restructured) =================
#define NS_MS    0             // 128 x 104 = 13312 words
#define NS_BM    13312
#define NS_GM    13408
#define NS_BT    13504
#define NS_TOTAL 13600
#define N_SMEM_BYTES (NS_TOTAL * 4)

__global__ void __launch_bounds__(256, 2) node_kernel_mma(
    const float* __restrict__ nodes, const float* __restrict__ bu,
    const float* __restrict__ gm,    const float* __restrict__ bt,
    float* __restrict__ upd_out)
{
    extern __shared__ float sm[];
    float* Ms   = sm + NS_MS;         // stride MSTR
    float* bm_s = sm + NS_BM;
    float* gm_s = sm + NS_GM;
    float* bt_s = sm + NS_BT;

    const int t = threadIdx.x;

    if (t < FIL) { bm_s[t] = bu[t]; gm_s[t] = gm[t]; bt_s[t] = bt[t]; }
    __syncthreads();

    const int lane = t & 31;
    const int w    = t >> 5;          // 0..7
    const int g    = lane >> 2;
    const int q    = lane & 3;
    const int r0 = w * 16 + g, r1 = r0 + 8;

    const int gn0 = blockIdx.x * 128 + r0;
    const int gn1 = gn0 + 8;
    const int g0c = gn0 < NT ? gn0 : NT - 1;
    const int g1c = gn1 < NT ? gn1 : NT - 1;
    const float* n0 = nodes + (size_t)g0c * Ff;
    const float* n1 = nodes + (size_t)g1c * Ff;
    const float* a0 = g_agg + (size_t)g0c * FIL;
    const float* a1 = g_agg + (size_t)g1c * FIL;

    float c[12][4];
    #pragma unroll
    for (int nt = 0; nt < 12; nt++) { c[nt][0]=0.f; c[nt][1]=0.f; c[nt][2]=0.f; c[nt][3]=0.f; }

    const int gsw = g ^ (2 * q);
    const int qo  = 2 * q;

    #pragma unroll
    for (int kt = 0; kt < 10; kt++) {
        const float *p0, *p1;
        int off;
        if (kt < 4) { p0 = n0; p1 = n1; off = kt * 16; }
        else        { p0 = a0; p1 = a1; off = (kt - 4) * 16; }
        off += qo;

        uint32_t ah[4], al[4];
        load_split(p0, off, ah[0], ah[2], al[0], al[2]);
        load_split(p1, off, ah[1], ah[3], al[1], al[3]);

        const uint4* Bp = g_Wun + (kt * 4 + q) * 96 + gsw;
        #pragma unroll
        for (int nt = 0; nt < 12; nt++) {
            uint4 Bv = Bp[nt * 8];
            mma_bf16(c[nt], ah, Bv.x, Bv.y);
            mma_bf16(c[nt], al, Bv.x, Bv.y);
            mma_bf16(c[nt], ah, Bv.z, Bv.w);
        }
    }

    // ---- bias + relu + LN stats (quad owns rows r0, r1) ----
    float sum0 = 0.f, sq0 = 0.f, sum1 = 0.f, sq1 = 0.f;
    #pragma unroll
    for (int nt = 0; nt < 12; nt++) {
        const int j = nt * 8 + qo;
        const float bv0 = bm_s[j], bv1 = bm_s[j + 1];
        float v0 = fmaxf(c[nt][0] + bv0, 0.f);
        float v1 = fmaxf(c[nt][1] + bv1, 0.f);
        float v2 = fmaxf(c[nt][2] + bv0, 0.f);
        float v3 = fmaxf(c[nt][3] + bv1, 0.f);
        c[nt][0] = v0; c[nt][1] = v1; c[nt][2] = v2; c[nt][3] = v3;
        sum0 += v0 + v1;  sq0 += v0 * v0 + v1 * v1;
        sum1 += v2 + v3;  sq1 += v2 * v2 + v3 * v3;
    }
    #pragma unroll
    for (int m = 1; m < 4; m <<= 1) {
        sum0 += __shfl_xor_sync(0xffffffffu, sum0, m);
        sq0  += __shfl_xor_sync(0xffffffffu, sq0,  m);
        sum1 += __shfl_xor_sync(0xffffffffu, sum1, m);
        sq1  += __shfl_xor_sync(0xffffffffu, sq1,  m);
    }
    const float mean0 = sum0 * (1.f / FIL);
    const float rstd0 = rsqrtf(sq0 * (1.f / FIL) - mean0 * mean0 + LN_EPS);
    const float mean1 = sum1 * (1.f / FIL);
    const float rstd1 = rsqrtf(sq1 * (1.f / FIL) - mean1 * mean1 + LN_EPS);

    // ---- apply LN, stage ----
    #pragma unroll
    for (int nt = 0; nt < 12; nt++) {
        const int j = nt * 8 + qo;
        const float g0 = gm_s[j], g1 = gm_s[j + 1];
        const float t0 = bt_s[j], t1 = bt_s[j + 1];
        *(float2*)(Ms + r0 * MSTR + j) = make_float2(
            (c[nt][0] - mean0) * rstd0 * g0 + t0,
            (c[nt][1] - mean0) * rstd0 * g1 + t1);
        *(float2*)(Ms + r1 * MSTR + j) = make_float2(
            (c[nt][2] - mean1) * rstd1 * g0 + t0,
            (c[nt][3] - mean1) * rstd1 * g1 + t1);
    }
    __syncthreads();

    // ---- coalesced store ----
    for (int i = t; i < 128 * 24; i += 256) {
        const int row = i / 24;
        const int c4  = i - row * 24;
        const int ge  = blockIdx.x * 128 + row;
        if (ge >= NT) continue;
        float4 o = *(const float4*)(Ms + row * MSTR + c4 * 4);
        ((float4*)(upd_out + (size_t)ge * FIL))[c4] = o;
    }
}

// ---------------- launch ----------------
extern "C" void kernel_launch(void* const* d_in, const int* in_sizes, int n_in,
                              void* d_out, int out_size) {
    const float* nodes = (const float*)d_in[0];
    const float* ef    = (const float*)d_in[1];
    const int*   edges = (const int*)  d_in[2];
    const float* Wm    = (const float*)d_in[3];
    const float* bm    = (const float*)d_in[4];
    const float* gm_m  = (const float*)d_in[5];
    const float* bt_m  = (const float*)d_in[6];
    const float* Wu    = (const float*)d_in[7];
    const float* bu    = (const float*)d_in[8];
    const float* gm_u  = (const float*)d_in[9];
    const float* bt_u  = (const float*)d_in[10];

    float* out = (float*)d_out;
    float* upd = out;                               // (B, N, FILTERS)
    float* msg = out + (size_t)Bq * Nn * FIL;       // (B, E, FILTERS)

    cudaFuncSetAttribute(edge_kernel_mma, cudaFuncAttributeMaxDynamicSharedMemorySize,
                         E_SMEM_BYTES);
    cudaFuncSetAttribute(node_kernel_mma, cudaFuncAttributeMaxDynamicSharedMemorySize,
                         N_SMEM_BYTES);

    pack_kernel<<<232, 256>>>(Wm, Wu);
    pre_kernel<<<(NT + 127) / 128, 256>>>(nodes);
    edge_kernel_mma<<<(Bq * Ee) / 128, 256, E_SMEM_BYTES>>>(
        ef, edges, bm, gm_m, bt_m, msg);
    node_kernel_mma<<<(NT + 127) / 128, 256, N_SMEM_BYTES>>>(
        nodes, bu, gm_u, bt_u, upd);
}